// round 7
// baseline (speedup 1.0000x reference)
#include <cuda_runtime.h>

#define NBR    8
#define BATCH  128
#define HID    512
#define TT     256
#define G4     (4*HID)     // 2048
#define KC     32          // K chunk
#define HS_PAD 132         // h_s row stride (floats): 132%32==4 -> conflict-free reads, 16B aligned rows
#define WS_PAD 36          // w_s row stride

// ---------------- device scratch (statically allocated, no runtime alloc) ----------------
__device__ __align__(16) float g_h[2][NBR*HID*BATCH];   // state h, layout [n][hid][b], ping-pong
__device__ __align__(16) float g_c[2][NBR*HID*BATCH];   // cell state, layout [n][hid][b]
__device__ __align__(16) float g_ys[TT*NBR*BATCH];      // ys[t][n][b] = h[n][b][HID-1] at step t
__device__ __align__(16) float g_wt[NBR*HID*G4];        // Whh transposed: [n][k][row], row in 0..2047

// ---------------- helpers ----------------
__device__ __forceinline__ unsigned long long dupf(float v) {
    unsigned long long r; unsigned u = __float_as_uint(v);
    asm("mov.b64 %0, {%1, %1};" : "=l"(r) : "r"(u));
    return r;
}
__device__ __forceinline__ void fma2(unsigned long long &d, unsigned long long a, unsigned long long b) {
    asm("fma.rn.f32x2 %0, %1, %2, %0;" : "+l"(d) : "l"(a), "l"(b));
}
__device__ __forceinline__ float lo32(unsigned long long a) { return __uint_as_float((unsigned)a); }
__device__ __forceinline__ float hi32(unsigned long long a) { return __uint_as_float((unsigned)(a >> 32)); }
__device__ __forceinline__ float pickl(unsigned long long a, int l) { return l ? hi32(a) : lo32(a); }
__device__ __forceinline__ float sigm(float x)  { return 1.0f / (1.0f + __expf(-x)); }
__device__ __forceinline__ float tanh_(float x) { return 2.0f / (1.0f + __expf(-2.0f * x)) - 1.0f; }

// ---------------- one-time per-call prep kernels ----------------
// g_wt[n][k][row] = Whh[n][row][k]   (write-coalesced; reads L2-resident after first touch)
__global__ void transpose_whh_kernel(const float* __restrict__ Whh) {
    size_t i = (size_t)blockIdx.x * blockDim.x + threadIdx.x;
    if (i >= (size_t)NBR * HID * G4) return;
    size_t row = i & (G4 - 1);
    size_t nk  = i >> 11;          // / 2048
    size_t k   = nk & (HID - 1);
    size_t n   = nk >> 9;          // / 512
    g_wt[i] = Whh[(n * G4 + row) * HID + k];
}

// g_h[0][n][j][b] = hn0[n][b][j] ; g_c[0] = 0
__global__ void init_kernel(const float* __restrict__ hn0) {
    int i = blockIdx.x * blockDim.x + threadIdx.x;
    if (i >= NBR * HID * BATCH) return;
    int b  = i & (BATCH - 1);
    int nj = i >> 7;
    int j  = nj & (HID - 1);
    int n  = nj >> 9;
    g_h[0][i] = hn0[(n * BATCH + b) * HID + j];
    g_c[0][i] = 0.0f;
}

// ---------------- one LSTM time step (all branches), f32x2-packed SGEMM + cell ----------------
// grid = 128 blocks: blockIdx.x = n*16 + jtile.  128 threads: tx = tid&15 (batch), ty = tid>>4 (j).
// Each thread: 4 gates x 4 j x 8 batch -> 64 packed f32x2 accumulators.
__global__ __launch_bounds__(128, 1)
void step_kernel(const float* __restrict__ Wih, const float* __restrict__ b_ih,
                 const float* __restrict__ b_hh, const float* __restrict__ cin, int t)
{
    __shared__ __align__(16) float h_s[KC][HS_PAD];         // [k][b]
    __shared__ __align__(16) float w_s[4][KC][WS_PAD];      // [gate][k][j]

    const int tid = threadIdx.x;
    const int tx  = tid & 15;
    const int ty  = tid >> 4;
    const int n   = blockIdx.x >> 4;
    const int j0  = (blockIdx.x & 15) * 32;
    const int s   = t & 1, dd = s ^ 1;

    const float* __restrict__ hold = &g_h[s][(size_t)n * HID * BATCH];
    const float* __restrict__ wtn  = &g_wt[(size_t)n * HID * G4];

    unsigned long long acc[4][4][4];   // [gate][jj][bpair]
    #pragma unroll
    for (int a0 = 0; a0 < 4; a0++)
        #pragma unroll
        for (int a1 = 0; a1 < 4; a1++)
            #pragma unroll
            for (int a2 = 0; a2 < 4; a2++) acc[a0][a1][a2] = 0ull;

    // loader mappings
    const int bf = tid & 31;   // h: float4 column over batch (32 quads = 128 b)
    const int kq = tid >> 5;   // h/w: k sub-row (0..3), 8 passes cover KC=32

    for (int kc = 0; kc < HID; kc += KC) {
        // load h chunk [KC][128]  (global layout [hid][b] -> direct copy, no transpose)
        #pragma unroll
        for (int p = 0; p < 8; p++) {
            int k = kq + p * 4;
            float4 v = *reinterpret_cast<const float4*>(hold + (size_t)(kc + k) * BATCH + bf * 4);
            *reinterpret_cast<float4*>(&h_s[k][bf * 4]) = v;
        }
        // load W chunk: w_s[gt][k][j] from g_wt[n][k][gt*512 + j0 + j]
        {
            int gt = bf >> 3;          // row-quad -> gate
            int jq = bf & 7;           // j quad within tile
            #pragma unroll
            for (int p = 0; p < 8; p++) {
                int k = kq + p * 4;
                float4 v = *reinterpret_cast<const float4*>(
                    wtn + (size_t)(kc + k) * G4 + gt * HID + j0 + jq * 4);
                *reinterpret_cast<float4*>(&w_s[gt][k][jq * 4]) = v;
            }
        }
        __syncthreads();

        #pragma unroll 8
        for (int k = 0; k < KC; k++) {
            ulonglong2 ha = *reinterpret_cast<const ulonglong2*>(&h_s[k][tx * 4]);
            ulonglong2 hb = *reinterpret_cast<const ulonglong2*>(&h_s[k][64 + tx * 4]);
            unsigned long long hp0 = ha.x, hp1 = ha.y, hp2 = hb.x, hp3 = hb.y;
            #pragma unroll
            for (int gt = 0; gt < 4; gt++) {
                float4 wv = *reinterpret_cast<const float4*>(&w_s[gt][k][ty * 4]);
                unsigned long long w;
                w = dupf(wv.x);
                fma2(acc[gt][0][0], w, hp0); fma2(acc[gt][0][1], w, hp1);
                fma2(acc[gt][0][2], w, hp2); fma2(acc[gt][0][3], w, hp3);
                w = dupf(wv.y);
                fma2(acc[gt][1][0], w, hp0); fma2(acc[gt][1][1], w, hp1);
                fma2(acc[gt][1][2], w, hp2); fma2(acc[gt][1][3], w, hp3);
                w = dupf(wv.z);
                fma2(acc[gt][2][0], w, hp0); fma2(acc[gt][2][1], w, hp1);
                fma2(acc[gt][2][2], w, hp2); fma2(acc[gt][2][3], w, hp3);
                w = dupf(wv.w);
                fma2(acc[gt][3][0], w, hp0); fma2(acc[gt][3][1], w, hp1);
                fma2(acc[gt][3][2], w, hp2); fma2(acc[gt][3][3], w, hp3);
            }
        }
        __syncthreads();
    }

    // ---- epilogue: add input term + bias, LSTM cell, write h/c (layout [n][j][b]) ----
    const int jc = j0 + ty * 4;
    float wih[4][4], bs_[4][4];
    #pragma unroll
    for (int gt = 0; gt < 4; gt++)
        #pragma unroll
        for (int jj = 0; jj < 4; jj++) {
            int row = n * G4 + gt * HID + jc + jj;
            wih[gt][jj] = Wih[row];
            bs_[gt][jj] = b_ih[row] + b_hh[row];
        }

    float xin[2][4];
    #pragma unroll
    for (int gh = 0; gh < 2; gh++)
        #pragma unroll
        for (int q = 0; q < 4; q++)
            xin[gh][q] = cin[(gh * 64 + tx * 4 + q) * TT + t];

    const size_t nHB = (size_t)n * HID * BATCH;
    #pragma unroll
    for (int jj = 0; jj < 4; jj++) {
        const int j = jc + jj;
        const size_t rb = nHB + (size_t)j * BATCH;
        #pragma unroll
        for (int gh = 0; gh < 2; gh++) {
            const int bb = gh * 64 + tx * 4;
            float4 cc4 = *reinterpret_cast<const float4*>(&g_c[s][rb + bb]);
            float cold[4] = {cc4.x, cc4.y, cc4.z, cc4.w};
            float hv[4], cv[4];
            #pragma unroll
            for (int q = 0; q < 4; q++) {
                const int pb = gh * 2 + (q >> 1);
                const int l  = q & 1;
                float gi = pickl(acc[0][jj][pb], l) + xin[gh][q] * wih[0][jj] + bs_[0][jj];
                float gf = pickl(acc[1][jj][pb], l) + xin[gh][q] * wih[1][jj] + bs_[1][jj];
                float gg = pickl(acc[2][jj][pb], l) + xin[gh][q] * wih[2][jj] + bs_[2][jj];
                float go = pickl(acc[3][jj][pb], l) + xin[gh][q] * wih[3][jj] + bs_[3][jj];
                float cc = sigm(gf) * cold[q] + sigm(gi) * tanh_(gg);
                cv[q] = cc;
                hv[q] = sigm(go) * tanh_(cc);
            }
            *reinterpret_cast<float4*>(&g_c[dd][rb + bb]) = make_float4(cv[0], cv[1], cv[2], cv[3]);
            *reinterpret_cast<float4*>(&g_h[dd][rb + bb]) = make_float4(hv[0], hv[1], hv[2], hv[3]);
            if (j == HID - 1) {
                #pragma unroll
                for (int q = 0; q < 4; q++)
                    g_ys[(size_t)t * NBR * BATCH + n * BATCH + bb + q] = hv[q];
            }
        }
    }
}

// ---------------- readout: out[b][k] = sum_t (sum_n ys[t,n,b]*x[n,b,t]) * Wl[k,t] + bl[k] ----------------
__global__ void final_kernel(const float* __restrict__ x, const float* __restrict__ Wl,
                             const float* __restrict__ bl, float* __restrict__ out)
{
    __shared__ float red[TT];
    const int b = blockIdx.x;
    const int t = threadIdx.x;     // 256 threads == TT
    float r = 0.0f;
    #pragma unroll
    for (int nn = 0; nn < NBR; nn++)
        r += g_ys[(size_t)t * NBR * BATCH + nn * BATCH + b] * x[(nn * BATCH + b) * TT + t];

    for (int k = 0; k < NBR; k++) {
        red[t] = r * Wl[k * TT + t];
        __syncthreads();
        for (int sft = TT / 2; sft > 0; sft >>= 1) {
            if (t < sft) red[t] += red[t + sft];
            __syncthreads();
        }
        if (t == 0) out[b * NBR + k] = red[0] + bl[k];
        __syncthreads();
    }
}

// ---------------- launch ----------------
extern "C" void kernel_launch(void* const* d_in, const int* in_sizes, int n_in,
                              void* d_out, int out_size)
{
    (void)in_sizes; (void)n_in; (void)out_size;
    const float* x    = (const float*)d_in[0];   // (8,128,256)
    const float* c    = (const float*)d_in[1];   // (128,256,1)
    const float* Wih  = (const float*)d_in[2];   // (8,2048,1)
    const float* Whh  = (const float*)d_in[3];   // (8,2048,512)
    const float* b_ih = (const float*)d_in[4];   // (8,2048)
    const float* b_hh = (const float*)d_in[5];   // (8,2048)
    const float* hn0  = (const float*)d_in[6];   // (8,128,512)
    const float* Wl   = (const float*)d_in[7];   // (8,256)
    const float* bl   = (const float*)d_in[8];   // (8,)
    float* out = (float*)d_out;                  // (128,8) float32

    transpose_whh_kernel<<<(NBR * HID * G4 + 255) / 256, 256>>>(Whh);
    init_kernel<<<(NBR * HID * BATCH + 255) / 256, 256>>>(hn0);
    for (int t = 0; t < TT; t++)
        step_kernel<<<128, 128>>>(Wih, b_ih, b_hh, c, t);
    final_kernel<<<BATCH, TT>>>(x, Wl, bl, out);
}

// round 9
// speedup vs baseline: 2.2776x; 2.2776x over previous
#include <cuda_runtime.h>
#include <cuda_bf16.h>
#include <cstdint>

#define NBR    8
#define BATCH  128
#define HID    512
#define TT     256
#define G4     2048

// ---------------- device scratch (static, no runtime alloc) ----------------
// h state bf16 hi/lo, layout [n][b][512 k], rows pre-swizzled per 64-k chunk:
// within chunk, 16B unit u stored at u ^ (b&7). Ping-pong on step parity.
__device__ __align__(16) __nv_bfloat16 g_hh[2][NBR*BATCH*HID];
__device__ __align__(16) __nv_bfloat16 g_hl[2][NBR*BATCH*HID];
// cell state fp32 [n][j][b] (CTA-exclusive slices)
__device__ __align__(16) float g_c[NBR*HID*BATCH];
__device__ __align__(16) float g_ys[TT*NBR*BATCH];
// Whh bf16 hi/lo pre-swizzled tiles: [split][n][jt][kchunk][row*8 + physunit]
// row = gate*32 + jj (128 rows), 64 k bf16 = 8 x 16B units, phys = u ^ (row&7)
__device__ __align__(16) uint4 g_wimg[2][NBR][16][8][1024];

// ---------------- helpers ----------------
__device__ __forceinline__ float sigm(float x)  { return 1.0f / (1.0f + __expf(-x)); }
__device__ __forceinline__ float tanh_(float x) { return 2.0f / (1.0f + __expf(-2.0f * x)) - 1.0f; }

__device__ __forceinline__ uint32_t smem_u32(const void* p) {
    uint32_t a;
    asm("{ .reg .u64 t; cvta.to.shared.u64 t, %1; cvt.u32.u64 %0, t; }" : "=r"(a) : "l"(p));
    return a;
}
__device__ __forceinline__ void cp16(uint32_t dst, const void* src) {
    asm volatile("cp.async.cg.shared.global [%0], [%1], 16;" :: "r"(dst), "l"(src) : "memory");
}
#define CP_COMMIT() asm volatile("cp.async.commit_group;" ::: "memory")
#define CP_WAIT(N)  asm volatile("cp.async.wait_group %0;" :: "n"(N) : "memory")

__device__ __forceinline__ void ldsm4(unsigned* r, uint32_t addr) {
    asm volatile("ldmatrix.sync.aligned.m8n8.x4.shared.b16 {%0,%1,%2,%3}, [%4];"
        : "=r"(r[0]), "=r"(r[1]), "=r"(r[2]), "=r"(r[3]) : "r"(addr));
}
__device__ __forceinline__ void mma16816(float* d, const unsigned* a, const unsigned* b) {
    asm volatile("mma.sync.aligned.m16n8k16.row.col.f32.bf16.bf16.f32 "
        "{%0,%1,%2,%3}, {%4,%5,%6,%7}, {%8,%9}, {%0,%1,%2,%3};"
        : "+f"(d[0]), "+f"(d[1]), "+f"(d[2]), "+f"(d[3])
        : "r"(a[0]), "r"(a[1]), "r"(a[2]), "r"(a[3]), "r"(b[0]), "r"(b[1]));
}

__device__ __forceinline__ void split2(float w0, float w1, unsigned& hi, unsigned& lo) {
    __nv_bfloat16 h0 = __float2bfloat16_rn(w0);
    __nv_bfloat16 h1 = __float2bfloat16_rn(w1);
    __nv_bfloat16 l0 = __float2bfloat16_rn(w0 - __bfloat162float(h0));
    __nv_bfloat16 l1 = __float2bfloat16_rn(w1 - __bfloat162float(h1));
    hi = (unsigned)__bfloat16_as_ushort(h0) | ((unsigned)__bfloat16_as_ushort(h1) << 16);
    lo = (unsigned)__bfloat16_as_ushort(l0) | ((unsigned)__bfloat16_as_ushort(l1) << 16);
}

// ---------------- SMEM layout ----------------
// stage s at s*65536: Ah 16K | Al 16K | Bh 16K | Bl 16K   (2 stages = 128K)
// OFF_GATES: float[128][129] = 66048   OFF_X: 512B
#define OFF_GATES 131072
#define OFF_X     197120
#define DSMEM_REQ (197632 + 1024)

// ---------------- prep: split+swizzle Whh tiles ----------------
__global__ void prep_w_kernel(const float* __restrict__ Whh) {
    unsigned i = blockIdx.x * blockDim.x + threadIdx.x;   // 2^20
    unsigned u = i & 7, row = (i >> 3) & 127, kc = (i >> 10) & 7;
    unsigned jt = (i >> 13) & 15, n = i >> 17;
    unsigned gate = row >> 5, jj = row & 31;
    const float* src = Whh + ((size_t)(n * G4 + gate * HID + jt * 32 + jj)) * HID + kc * 64 + u * 8;
    float4 a = *(const float4*)src, b = *(const float4*)(src + 4);
    float w[8] = {a.x, a.y, a.z, a.w, b.x, b.y, b.z, b.w};
    unsigned hi[4], lo[4];
    #pragma unroll
    for (int m = 0; m < 4; m++) split2(w[2*m], w[2*m+1], hi[m], lo[m]);
    unsigned phys = u ^ (row & 7);
    g_wimg[0][n][jt][kc][row * 8 + phys] = make_uint4(hi[0], hi[1], hi[2], hi[3]);
    g_wimg[1][n][jt][kc][row * 8 + phys] = make_uint4(lo[0], lo[1], lo[2], lo[3]);
}

// ---------------- prep: h0 split+swizzle, c = 0 ----------------
__global__ void prep_h_kernel(const float* __restrict__ hn0) {
    unsigned i = blockIdx.x * blockDim.x + threadIdx.x;   // 65536
    unsigned ug = i & 63, b = (i >> 6) & 127, n = i >> 13;
    const float* src = hn0 + ((size_t)(n * 128 + b)) * 512 + ug * 8;
    unsigned hi[4], lo[4];
    #pragma unroll
    for (int m = 0; m < 4; m++) split2(src[2*m], src[2*m+1], hi[m], lo[m]);
    unsigned chunk = ug >> 3, ul = ug & 7, phys = ul ^ (b & 7);
    size_t idx = ((size_t)(n * 128 + b)) * 64 + chunk * 8 + phys;
    ((uint4*)g_hh[0])[idx] = make_uint4(hi[0], hi[1], hi[2], hi[3]);
    ((uint4*)g_hl[0])[idx] = make_uint4(lo[0], lo[1], lo[2], lo[3]);
    #pragma unroll
    for (int q = 0; q < 8; q++) g_c[(size_t)i * 8 + q] = 0.0f;
}

// ---------------- one LSTM step: HMMA bf16-split GEMM + cell ----------------
// grid 128 = n*16 + jt. 256 threads / 8 warps; warp = (gate, batch-half).
__global__ __launch_bounds__(256, 1)
void step_kernel(const float* __restrict__ Wih, const float* __restrict__ b_ih,
                 const float* __restrict__ b_hh, const float* __restrict__ cin, int t)
{
    extern __shared__ __align__(16) unsigned char smem_raw[];
    uint32_t sb = smem_u32(smem_raw);
    uint32_t base = (sb + 1023) & ~1023u;
    unsigned char* bp = smem_raw + (base - sb);

    const int tid = threadIdx.x, wid = tid >> 5, lane = tid & 31;
    const int n = blockIdx.x >> 4, jt = blockIdx.x & 15;
    const int s = t & 1, dd = s ^ 1;
    const int g = wid >> 1, bh = wid & 1;

    float* smg = (float*)(bp + OFF_GATES);
    float* smx = (float*)(bp + OFF_X);
    if (tid < 128) smx[tid] = cin[tid * TT + t];

    const uint4* srcA0 = &g_wimg[0][n][jt][0][0];
    const uint4* srcA1 = &g_wimg[1][n][jt][0][0];
    const uint4* srcBh = (const uint4*)g_hh[s] + (size_t)n * BATCH * 64;
    const uint4* srcBl = (const uint4*)g_hl[s] + (size_t)n * BATCH * 64;

    float acc[2][8][4];
    #pragma unroll
    for (int a0 = 0; a0 < 2; a0++)
        #pragma unroll
        for (int a1 = 0; a1 < 8; a1++)
            #pragma unroll
            for (int a2 = 0; a2 < 4; a2++) acc[a0][a1][a2] = 0.0f;

    // lane-derived fragment addressing
    const int aro = (lane & 7) + ((lane >> 3) & 1) * 8;  // + g*32 + mt*16
    const int auh = lane >> 4;
    const int bro = (lane & 7) + ((lane >> 4) & 1) * 8;  // + bh*64 + nb*16
    const int buh = (lane >> 3) & 1;

    // prologue: chunk 0 -> stage 0
    {
        uint32_t dst = base;
        #pragma unroll
        for (int r = 0; r < 4; r++) {
            int i = r * 256 + tid;
            int b_ = i >> 3, u = i & 7;
            cp16(dst + i * 16,         srcA0 + i);
            cp16(dst + 16384 + i * 16, srcA1 + i);
            cp16(dst + 32768 + i * 16, srcBh + b_ * 64 + u);
            cp16(dst + 49152 + i * 16, srcBl + b_ * 64 + u);
        }
        CP_COMMIT();
    }

    for (int kc = 0; kc < 8; kc++) {
        if (kc < 7) {
            uint32_t dst = base + (uint32_t)((kc + 1) & 1) * 65536u;
            #pragma unroll
            for (int r = 0; r < 4; r++) {
                int i = r * 256 + tid;
                int b_ = i >> 3, u = i & 7;
                cp16(dst + i * 16,         srcA0 + (kc + 1) * 1024 + i);
                cp16(dst + 16384 + i * 16, srcA1 + (kc + 1) * 1024 + i);
                cp16(dst + 32768 + i * 16, srcBh + b_ * 64 + (kc + 1) * 8 + u);
                cp16(dst + 49152 + i * 16, srcBl + b_ * 64 + (kc + 1) * 8 + u);
            }
            CP_COMMIT();
            CP_WAIT(1);
        } else {
            CP_WAIT(0);
        }
        __syncthreads();

        const uint32_t tb = base + (uint32_t)(kc & 1) * 65536u;
        #pragma unroll
        for (int ks = 0; ks < 4; ks++) {
            unsigned Ah[2][4], Al[2][4], Bh[4][4], Bl[4][4];
            #pragma unroll
            for (int mt = 0; mt < 2; mt++) {
                int row = g * 32 + mt * 16 + aro;
                int u = ks * 2 + auh;
                uint32_t ad = tb + row * 128 + ((u ^ (row & 7)) << 4);
                ldsm4(Ah[mt], ad);
                ldsm4(Al[mt], ad + 16384);
            }
            #pragma unroll
            for (int nb = 0; nb < 4; nb++) {
                int row = bh * 64 + nb * 16 + bro;
                int u = ks * 2 + buh;
                uint32_t ad = tb + 32768 + row * 128 + ((u ^ (row & 7)) << 4);
                ldsm4(Bh[nb], ad);
                ldsm4(Bl[nb], ad + 16384);
            }
            #pragma unroll
            for (int mt = 0; mt < 2; mt++)
                #pragma unroll
                for (int nt = 0; nt < 8; nt++) {
                    const unsigned* bhp = &Bh[nt >> 1][(nt & 1) * 2];
                    const unsigned* blp = &Bl[nt >> 1][(nt & 1) * 2];
                    mma16816(acc[mt][nt], Ah[mt], bhp);
                    mma16816(acc[mt][nt], Ah[mt], blp);
                    mma16816(acc[mt][nt], Al[mt], bhp);
                }
        }
        __syncthreads();
    }

    // ---- epilogue: fp32 input term + bias, activation, stage gates in smem ----
    float wv[2][2], bsv[2][2];
    #pragma unroll
    for (int mt = 0; mt < 2; mt++)
        #pragma unroll
        for (int h2 = 0; h2 < 2; h2++) {
            int rg = n * G4 + g * HID + jt * 32 + mt * 16 + (lane >> 2) + h2 * 8;
            wv[mt][h2]  = Wih[rg];
            bsv[mt][h2] = b_ih[rg] + b_hh[rg];
        }
    #pragma unroll
    for (int mt = 0; mt < 2; mt++) {
        int r0 = g * 32 + mt * 16 + (lane >> 2);
        #pragma unroll
        for (int nt = 0; nt < 8; nt++) {
            int col = bh * 64 + nt * 8 + (lane & 3) * 2;
            float x0 = smx[col], x1 = smx[col + 1];
            float v00 = acc[mt][nt][0] + x0 * wv[mt][0] + bsv[mt][0];
            float v01 = acc[mt][nt][1] + x1 * wv[mt][0] + bsv[mt][0];
            float v10 = acc[mt][nt][2] + x0 * wv[mt][1] + bsv[mt][1];
            float v11 = acc[mt][nt][3] + x1 * wv[mt][1] + bsv[mt][1];
            if (g == 2) { v00 = tanh_(v00); v01 = tanh_(v01); v10 = tanh_(v10); v11 = tanh_(v11); }
            else        { v00 = sigm(v00);  v01 = sigm(v01);  v10 = sigm(v10);  v11 = sigm(v11);  }
            smg[r0 * 129 + col]       = v00;
            smg[r0 * 129 + col + 1]   = v01;
            smg[(r0 + 8) * 129 + col]     = v10;
            smg[(r0 + 8) * 129 + col + 1] = v11;
        }
    }
    __syncthreads();

    // ---- cell update: thread = (batch b, j half) ----
    {
        const int b = tid & 127, half = tid >> 7;
        const int j0 = half * 16;
        float* cptr = g_c + ((size_t)n * HID + jt * 32 + j0) * BATCH + b;
        unsigned ph[8], pl[8];
        float hlast = 0.0f;
        #pragma unroll
        for (int q = 0; q < 16; q++) {
            int jj = j0 + q;
            float gi = smg[jj * 129 + b];
            float gf = smg[(32 + jj) * 129 + b];
            float gg = smg[(64 + jj) * 129 + b];
            float go = smg[(96 + jj) * 129 + b];
            float cold = cptr[q * BATCH];
            float cn = gf * cold + gi * gg;
            cptr[q * BATCH] = cn;
            float h = go * tanh_(cn);
            hlast = h;
            __nv_bfloat16 bhf = __float2bfloat16_rn(h);
            __nv_bfloat16 blf = __float2bfloat16_rn(h - __bfloat162float(bhf));
            unsigned uh = __bfloat16_as_ushort(bhf), ulw = __bfloat16_as_ushort(blf);
            if (q & 1) { ph[q >> 1] |= uh << 16; pl[q >> 1] |= ulw << 16; }
            else       { ph[q >> 1]  = uh;       pl[q >> 1]  = ulw;       }
        }
        int uq0 = jt * 4 + half * 2;          // global 16B-unit index of j0
        int chunk = uq0 >> 3;
        int ul0 = uq0 & 7, ul1 = (uq0 + 1) & 7;
        int bx = b & 7;
        size_t rowbase = ((size_t)n * BATCH + b) * 64 + chunk * 8;
        uint4* oh = (uint4*)g_hh[dd];
        uint4* ol = (uint4*)g_hl[dd];
        oh[rowbase + (ul0 ^ bx)] = make_uint4(ph[0], ph[1], ph[2], ph[3]);
        oh[rowbase + (ul1 ^ bx)] = make_uint4(ph[4], ph[5], ph[6], ph[7]);
        ol[rowbase + (ul0 ^ bx)] = make_uint4(pl[0], pl[1], pl[2], pl[3]);
        ol[rowbase + (ul1 ^ bx)] = make_uint4(pl[4], pl[5], pl[6], pl[7]);
        if (jt == 15 && half == 1)
            g_ys[(size_t)t * NBR * BATCH + n * BATCH + b] = hlast;
    }
}

// ---------------- readout ----------------
__global__ void final_kernel(const float* __restrict__ x, const float* __restrict__ Wl,
                             const float* __restrict__ bl, float* __restrict__ out)
{
    __shared__ float red[TT];
    const int b = blockIdx.x;
    const int t = threadIdx.x;
    float r = 0.0f;
    #pragma unroll
    for (int nn = 0; nn < NBR; nn++)
        r += g_ys[(size_t)t * NBR * BATCH + nn * BATCH + b] * x[(nn * BATCH + b) * TT + t];
    for (int k = 0; k < NBR; k++) {
        red[t] = r * Wl[k * TT + t];
        __syncthreads();
        for (int sft = TT / 2; sft > 0; sft >>= 1) {
            if (t < sft) red[t] += red[t + sft];
            __syncthreads();
        }
        if (t == 0) out[b * NBR + k] = red[0] + bl[k];
        __syncthreads();
    }
}

// ---------------- launch ----------------
extern "C" void kernel_launch(void* const* d_in, const int* in_sizes, int n_in,
                              void* d_out, int out_size)
{
    (void)in_sizes; (void)n_in; (void)out_size;
    const float* x    = (const float*)d_in[0];
    const float* c    = (const float*)d_in[1];
    const float* Wih  = (const float*)d_in[2];
    const float* Whh  = (const float*)d_in[3];
    const float* b_ih = (const float*)d_in[4];
    const float* b_hh = (const float*)d_in[5];
    const float* hn0  = (const float*)d_in[6];
    const float* Wl   = (const float*)d_in[7];
    const float* bl   = (const float*)d_in[8];
    float* out = (float*)d_out;

    static bool attr_set = false;
    if (!attr_set) {
        cudaFuncSetAttribute(step_kernel, cudaFuncAttributeMaxDynamicSharedMemorySize, DSMEM_REQ);
        attr_set = true;
    }

    prep_w_kernel<<<4096, 256>>>(Whh);
    prep_h_kernel<<<256, 256>>>(hn0);
    for (int t = 0; t < TT; t++)
        step_kernel<<<128, 256, DSMEM_REQ>>>(Wih, b_ih, b_hh, c, t);
    final_kernel<<<BATCH, TT>>>(x, Wl, bl, out);
}

// round 10
// speedup vs baseline: 2.4900x; 1.0932x over previous
#include <cuda_runtime.h>
#include <cuda_bf16.h>
#include <cstdint>

#define NBR    8
#define BATCH  128
#define HID    512
#define TT     256
#define G4     2048

// ---------------- device scratch (static, no runtime alloc) ----------------
// h state bf16 hi/lo, layout [n][b][512 k], rows pre-swizzled per 64-k chunk:
// within chunk, 16B unit u stored at u ^ (b&7). Ping-pong on step parity.
__device__ __align__(16) __nv_bfloat16 g_hh[2][NBR*BATCH*HID];
__device__ __align__(16) __nv_bfloat16 g_hl[2][NBR*BATCH*HID];
__device__ __align__(16) float g_ys[TT*NBR*BATCH];
__device__ __align__(16) float g_xt[TT*BATCH];          // x transposed: [t][b]
__device__ unsigned g_bar[NBR*32];                      // per-branch barrier counters (padded)
// Whh bf16 hi/lo pre-swizzled tiles: [split][n][jt][kchunk][row*8 + physunit]
__device__ __align__(16) uint4 g_wimg[2][NBR][16][8][1024];

// ---------------- helpers ----------------
__device__ __forceinline__ float sigm(float x)  { return 1.0f / (1.0f + __expf(-x)); }
__device__ __forceinline__ float tanh_(float x) { return 2.0f / (1.0f + __expf(-2.0f * x)) - 1.0f; }

__device__ __forceinline__ uint32_t smem_u32(const void* p) {
    uint32_t a;
    asm("{ .reg .u64 t; cvta.to.shared.u64 t, %1; cvt.u32.u64 %0, t; }" : "=r"(a) : "l"(p));
    return a;
}
__device__ __forceinline__ void cp16(uint32_t dst, const void* src) {
    asm volatile("cp.async.cg.shared.global [%0], [%1], 16;" :: "r"(dst), "l"(src) : "memory");
}
#define CP_COMMIT() asm volatile("cp.async.commit_group;" ::: "memory")
#define CP_WAIT(N)  asm volatile("cp.async.wait_group %0;" :: "n"(N) : "memory")

__device__ __forceinline__ void ldsm4(unsigned* r, uint32_t addr) {
    asm volatile("ldmatrix.sync.aligned.m8n8.x4.shared.b16 {%0,%1,%2,%3}, [%4];"
        : "=r"(r[0]), "=r"(r[1]), "=r"(r[2]), "=r"(r[3]) : "r"(addr));
}
__device__ __forceinline__ void mma16816(float* d, const unsigned* a, const unsigned* b) {
    asm volatile("mma.sync.aligned.m16n8k16.row.col.f32.bf16.bf16.f32 "
        "{%0,%1,%2,%3}, {%4,%5,%6,%7}, {%8,%9}, {%0,%1,%2,%3};"
        : "+f"(d[0]), "+f"(d[1]), "+f"(d[2]), "+f"(d[3])
        : "r"(a[0]), "r"(a[1]), "r"(a[2]), "r"(a[3]), "r"(b[0]), "r"(b[1]));
}
__device__ __forceinline__ void split2(float w0, float w1, unsigned& hi, unsigned& lo) {
    __nv_bfloat16 h0 = __float2bfloat16_rn(w0);
    __nv_bfloat16 h1 = __float2bfloat16_rn(w1);
    __nv_bfloat16 l0 = __float2bfloat16_rn(w0 - __bfloat162float(h0));
    __nv_bfloat16 l1 = __float2bfloat16_rn(w1 - __bfloat162float(h1));
    hi = (unsigned)__bfloat16_as_ushort(h0) | ((unsigned)__bfloat16_as_ushort(h1) << 16);
    lo = (unsigned)__bfloat16_as_ushort(l0) | ((unsigned)__bfloat16_as_ushort(l1) << 16);
}

// ---------------- SMEM layout ----------------
// stage s at s*65536: Ah 16K | Al 16K | Bh 16K | Bl 16K   (2 stages = 128K)
#define OFF_GATES 131072      // float[128][129] = 66048
#define OFF_X     197120      // 512 B
#define OFF_C     197632      // float[32][128] = 16384
#define DSMEM_REQ (214016 + 1024)

// ---------------- prep: split+swizzle Whh tiles ----------------
__global__ void prep_w_kernel(const float* __restrict__ Whh) {
    unsigned i = blockIdx.x * blockDim.x + threadIdx.x;   // 2^20
    unsigned u = i & 7, row = (i >> 3) & 127, kc = (i >> 10) & 7;
    unsigned jt = (i >> 13) & 15, n = i >> 17;
    unsigned gate = row >> 5, jj = row & 31;
    const float* src = Whh + ((size_t)(n * G4 + gate * HID + jt * 32 + jj)) * HID + kc * 64 + u * 8;
    float4 a = *(const float4*)src, b = *(const float4*)(src + 4);
    float w[8] = {a.x, a.y, a.z, a.w, b.x, b.y, b.z, b.w};
    unsigned hi[4], lo[4];
    #pragma unroll
    for (int m = 0; m < 4; m++) split2(w[2*m], w[2*m+1], hi[m], lo[m]);
    unsigned phys = u ^ (row & 7);
    g_wimg[0][n][jt][kc][row * 8 + phys] = make_uint4(hi[0], hi[1], hi[2], hi[3]);
    g_wimg[1][n][jt][kc][row * 8 + phys] = make_uint4(lo[0], lo[1], lo[2], lo[3]);
}

// ---------------- prep: h0 split+swizzle, barrier reset ----------------
__global__ void prep_h_kernel(const float* __restrict__ hn0) {
    unsigned i = blockIdx.x * blockDim.x + threadIdx.x;   // 65536
    unsigned ug = i & 63, b = (i >> 6) & 127, n = i >> 13;
    const float* src = hn0 + ((size_t)(n * 128 + b)) * 512 + ug * 8;
    unsigned hi[4], lo[4];
    #pragma unroll
    for (int m = 0; m < 4; m++) split2(src[2*m], src[2*m+1], hi[m], lo[m]);
    unsigned chunk = ug >> 3, ul = ug & 7, phys = ul ^ (b & 7);
    size_t idx = ((size_t)(n * 128 + b)) * 64 + chunk * 8 + phys;
    ((uint4*)g_hh[0])[idx] = make_uint4(hi[0], hi[1], hi[2], hi[3]);
    ((uint4*)g_hl[0])[idx] = make_uint4(lo[0], lo[1], lo[2], lo[3]);
    if (i < NBR * 32) g_bar[i] = 0;
}

// ---------------- prep: transpose x for coalesced step loads ----------------
__global__ void prep_x_kernel(const float* __restrict__ cin) {
    unsigned i = blockIdx.x * blockDim.x + threadIdx.x;   // 32768
    unsigned b = i & 127, t = i >> 7;
    g_xt[t * BATCH + b] = cin[b * TT + t];
}

// ---------------- cp.async issue helpers ----------------
__device__ __forceinline__ void issue_W(uint32_t dst, const uint4* srcA0, const uint4* srcA1,
                                        int kc, int tid) {
    #pragma unroll
    for (int r = 0; r < 4; r++) {
        int i = r * 256 + tid;
        cp16(dst + i * 16,         srcA0 + kc * 1024 + i);
        cp16(dst + 16384 + i * 16, srcA1 + kc * 1024 + i);
    }
}
__device__ __forceinline__ void issue_B(uint32_t dst, const uint4* srcBh, const uint4* srcBl,
                                        int kc, int tid) {
    #pragma unroll
    for (int r = 0; r < 4; r++) {
        int i = r * 256 + tid;
        int b_ = i >> 3, u = i & 7;
        cp16(dst + 32768 + i * 16, srcBh + b_ * 64 + kc * 8 + u);
        cp16(dst + 49152 + i * 16, srcBl + b_ * 64 + kc * 8 + u);
    }
}

// ---------------- fragment loads ----------------
__device__ __forceinline__ void load_frags(uint32_t tb, int ks, int g, int bh,
    int aro, int auh, int bro, int buh,
    unsigned (&Ah)[2][4], unsigned (&Al)[2][4], unsigned (&Bh)[4][4], unsigned (&Bl)[4][4])
{
    #pragma unroll
    for (int mt = 0; mt < 2; mt++) {
        int row = g * 32 + mt * 16 + aro;
        int u = ks * 2 + auh;
        uint32_t ad = tb + row * 128 + ((u ^ (row & 7)) << 4);
        ldsm4(Ah[mt], ad);
        ldsm4(Al[mt], ad + 16384);
    }
    #pragma unroll
    for (int nb = 0; nb < 4; nb++) {
        int row = bh * 64 + nb * 16 + bro;
        int u = ks * 2 + buh;
        uint32_t ad = tb + 32768 + row * 128 + ((u ^ (row & 7)) << 4);
        ldsm4(Bh[nb], ad);
        ldsm4(Bl[nb], ad + 16384);
    }
}

// ---------------- persistent kernel: all 256 LSTM steps ----------------
// grid 128 = n*16 + jt. 256 threads / 8 warps; warp = (gate, batch-half).
__global__ __launch_bounds__(256, 1)
void steps_kernel(const float* __restrict__ Wih, const float* __restrict__ b_ih,
                  const float* __restrict__ b_hh)
{
    extern __shared__ __align__(16) unsigned char smem_raw[];
    uint32_t sb = smem_u32(smem_raw);
    uint32_t base = (sb + 1023) & ~1023u;
    unsigned char* bp = smem_raw + (base - sb);

    const int tid = threadIdx.x, wid = tid >> 5, lane = tid & 31;
    const int n = blockIdx.x >> 4, jt = blockIdx.x & 15;
    const int g = wid >> 1, bh = wid & 1;

    float* smg = (float*)(bp + OFF_GATES);
    float* smx = (float*)(bp + OFF_X);
    float* smc = (float*)(bp + OFF_C);

    // init cell state (smem-resident across all steps)
    #pragma unroll
    for (int i = tid; i < 32 * BATCH; i += 256) smc[i] = 0.0f;

    // lane-derived fragment addressing
    const int aro = (lane & 7) + ((lane >> 3) & 1) * 8;
    const int auh = lane >> 4;
    const int bro = (lane & 7) + ((lane >> 4) & 1) * 8;
    const int buh = (lane >> 3) & 1;

    // hoisted epilogue constants
    float wv[2][2], bsv[2][2];
    #pragma unroll
    for (int mt = 0; mt < 2; mt++)
        #pragma unroll
        for (int h2 = 0; h2 < 2; h2++) {
            int rg = n * G4 + g * HID + jt * 32 + mt * 16 + (lane >> 2) + h2 * 8;
            wv[mt][h2]  = Wih[rg];
            bsv[mt][h2] = b_ih[rg] + b_hh[rg];
        }

    const uint4* srcA0 = &g_wimg[0][n][jt][0][0];
    const uint4* srcA1 = &g_wimg[1][n][jt][0][0];

    // prologue: W chunk 0 -> stage 0
    issue_W(base, srcA0, srcA1, 0, tid);
    CP_COMMIT();

    for (int t = 0; t < TT; t++) {
        const int s = t & 1, dd = s ^ 1;
        const uint4* srcBh = (const uint4*)g_hh[s] + (size_t)n * BATCH * 64;
        const uint4* srcBl = (const uint4*)g_hl[s] + (size_t)n * BATCH * 64;

        if (tid < 128) smx[tid] = g_xt[t * BATCH + tid];
        issue_B(base, srcBh, srcBl, 0, tid);
        CP_COMMIT();

        float acc[2][8][4];
        #pragma unroll
        for (int a0 = 0; a0 < 2; a0++)
            #pragma unroll
            for (int a1 = 0; a1 < 8; a1++)
                #pragma unroll
                for (int a2 = 0; a2 < 4; a2++) acc[a0][a1][a2] = 0.0f;

        for (int kc = 0; kc < 8; kc++) {
            if (kc < 7) {
                uint32_t dst = base + (uint32_t)((kc + 1) & 1) * 65536u;
                issue_W(dst, srcA0, srcA1, kc + 1, tid);
                issue_B(dst, srcBh, srcBl, kc + 1, tid);
                CP_COMMIT();
                CP_WAIT(1);
            } else if (t < TT - 1) {
                // prefetch next step's W chunk 0 under chunk-7 MMA + barrier
                issue_W(base, srcA0, srcA1, 0, tid);
                CP_COMMIT();
                CP_WAIT(1);
            } else {
                CP_WAIT(0);
            }
            __syncthreads();

            const uint32_t tb = base + (uint32_t)(kc & 1) * 65536u;
            unsigned Ah[2][2][4], Al[2][2][4], Bhf[2][4][4], Blf[2][4][4];
            load_frags(tb, 0, g, bh, aro, auh, bro, buh, Ah[0], Al[0], Bhf[0], Blf[0]);
            #pragma unroll
            for (int ks = 0; ks < 4; ks++) {
                const int cur = ks & 1;
                if (ks < 3)
                    load_frags(tb, ks + 1, g, bh, aro, auh, bro, buh,
                               Ah[cur ^ 1], Al[cur ^ 1], Bhf[cur ^ 1], Blf[cur ^ 1]);
                #pragma unroll
                for (int mt = 0; mt < 2; mt++)
                    #pragma unroll
                    for (int nt = 0; nt < 8; nt++) {
                        const unsigned* bhp = &Bhf[cur][nt >> 1][(nt & 1) * 2];
                        const unsigned* blp = &Blf[cur][nt >> 1][(nt & 1) * 2];
                        mma16816(acc[mt][nt], Ah[cur][mt], bhp);
                        mma16816(acc[mt][nt], Ah[cur][mt], blp);
                        mma16816(acc[mt][nt], Al[cur][mt], bhp);
                    }
            }
            __syncthreads();
        }

        // ---- epilogue: fp32 input term + bias, activation, stage gates in smem ----
        #pragma unroll
        for (int mt = 0; mt < 2; mt++) {
            int r0 = g * 32 + mt * 16 + (lane >> 2);
            #pragma unroll
            for (int nt = 0; nt < 8; nt++) {
                int col = bh * 64 + nt * 8 + (lane & 3) * 2;
                float x0 = smx[col], x1 = smx[col + 1];
                float v00 = acc[mt][nt][0] + x0 * wv[mt][0] + bsv[mt][0];
                float v01 = acc[mt][nt][1] + x1 * wv[mt][0] + bsv[mt][0];
                float v10 = acc[mt][nt][2] + x0 * wv[mt][1] + bsv[mt][1];
                float v11 = acc[mt][nt][3] + x1 * wv[mt][1] + bsv[mt][1];
                if (g == 2) { v00 = tanh_(v00); v01 = tanh_(v01); v10 = tanh_(v10); v11 = tanh_(v11); }
                else        { v00 = sigm(v00);  v01 = sigm(v01);  v10 = sigm(v10);  v11 = sigm(v11);  }
                smg[r0 * 129 + col]           = v00;
                smg[r0 * 129 + col + 1]       = v01;
                smg[(r0 + 8) * 129 + col]     = v10;
                smg[(r0 + 8) * 129 + col + 1] = v11;
            }
        }
        __syncthreads();

        // ---- cell update: thread = (batch b, j half); c in smem ----
        {
            const int b = tid & 127, half = tid >> 7;
            const int j0 = half * 16;
            unsigned ph[8], pl[8];
            float hlast = 0.0f;
            #pragma unroll
            for (int q = 0; q < 16; q++) {
                int jj = j0 + q;
                float gi = smg[jj * 129 + b];
                float gf = smg[(32 + jj) * 129 + b];
                float gg = smg[(64 + jj) * 129 + b];
                float go = smg[(96 + jj) * 129 + b];
                float cold = smc[jj * BATCH + b];
                float cn = gf * cold + gi * gg;
                smc[jj * BATCH + b] = cn;
                float h = go * tanh_(cn);
                hlast = h;
                __nv_bfloat16 bhf = __float2bfloat16_rn(h);
                __nv_bfloat16 blf = __float2bfloat16_rn(h - __bfloat162float(bhf));
                unsigned uh = __bfloat16_as_ushort(bhf), ulw = __bfloat16_as_ushort(blf);
                if (q & 1) { ph[q >> 1] |= uh << 16; pl[q >> 1] |= ulw << 16; }
                else       { ph[q >> 1]  = uh;       pl[q >> 1]  = ulw;       }
            }
            int uq0 = jt * 4 + half * 2;
            int chunk = uq0 >> 3;
            int ul0 = uq0 & 7, ul1 = (uq0 + 1) & 7;
            int bx = b & 7;
            size_t rowbase = ((size_t)n * BATCH + b) * 64 + chunk * 8;
            uint4* oh = (uint4*)g_hh[dd];
            uint4* ol = (uint4*)g_hl[dd];
            oh[rowbase + (ul0 ^ bx)] = make_uint4(ph[0], ph[1], ph[2], ph[3]);
            oh[rowbase + (ul1 ^ bx)] = make_uint4(ph[4], ph[5], ph[6], ph[7]);
            ol[rowbase + (ul0 ^ bx)] = make_uint4(pl[0], pl[1], pl[2], pl[3]);
            ol[rowbase + (ul1 ^ bx)] = make_uint4(pl[4], pl[5], pl[6], pl[7]);
            if (jt == 15 && half == 1)
                g_ys[(size_t)t * NBR * BATCH + n * BATCH + b] = hlast;
        }
        __syncthreads();

        // ---- per-branch barrier (16 CTAs), monotonic counter ----
        if (t < TT - 1) {
            if (tid == 0) {
                __threadfence();
                atomicAdd(&g_bar[n * 32], 1u);
                const unsigned tgt = 16u * (unsigned)(t + 1);
                unsigned v;
                do {
                    asm volatile("ld.acquire.gpu.global.u32 %0, [%1];"
                        : "=r"(v) : "l"(g_bar + n * 32) : "memory");
                } while (v < tgt);
            }
            __syncthreads();
        }
    }
}

// ---------------- readout ----------------
__global__ void final_kernel(const float* __restrict__ x, const float* __restrict__ Wl,
                             const float* __restrict__ bl, float* __restrict__ out)
{
    __shared__ float red[TT];
    const int b = blockIdx.x;
    const int t = threadIdx.x;
    float r = 0.0f;
    #pragma unroll
    for (int nn = 0; nn < NBR; nn++)
        r += g_ys[(size_t)t * NBR * BATCH + nn * BATCH + b] * x[(nn * BATCH + b) * TT + t];
    for (int k = 0; k < NBR; k++) {
        red[t] = r * Wl[k * TT + t];
        __syncthreads();
        for (int sft = TT / 2; sft > 0; sft >>= 1) {
            if (t < sft) red[t] += red[t + sft];
            __syncthreads();
        }
        if (t == 0) out[b * NBR + k] = red[0] + bl[k];
        __syncthreads();
    }
}

// ---------------- launch ----------------
extern "C" void kernel_launch(void* const* d_in, const int* in_sizes, int n_in,
                              void* d_out, int out_size)
{
    (void)in_sizes; (void)n_in; (void)out_size;
    const float* x    = (const float*)d_in[0];
    const float* c    = (const float*)d_in[1];
    const float* Wih  = (const float*)d_in[2];
    const float* Whh  = (const float*)d_in[3];
    const float* b_ih = (const float*)d_in[4];
    const float* b_hh = (const float*)d_in[5];
    const float* hn0  = (const float*)d_in[6];
    const float* Wl   = (const float*)d_in[7];
    const float* bl   = (const float*)d_in[8];
    float* out = (float*)d_out;

    static bool attr_set = false;
    if (!attr_set) {
        cudaFuncSetAttribute(steps_kernel, cudaFuncAttributeMaxDynamicSharedMemorySize, DSMEM_REQ);
        attr_set = true;
    }

    prep_w_kernel<<<4096, 256>>>(Whh);
    prep_h_kernel<<<256, 256>>>(hn0);
    prep_x_kernel<<<128, 256>>>(c);
    steps_kernel<<<128, 256, DSMEM_REQ>>>(Wih, b_ih, b_hh);
    final_kernel<<<BATCH, TT>>>(x, Wl, bl, out);
}

// round 11
// speedup vs baseline: 2.5818x; 1.0369x over previous
#include <cuda_runtime.h>
#include <cuda_bf16.h>
#include <cstdint>

#define NBR    8
#define BATCH  128
#define HID    512
#define TT     256
#define G4     2048

// ---------------- device scratch (static, no runtime alloc) ----------------
// h state bf16 hi/lo, layout [n][b][512 k], rows pre-swizzled per 64-k chunk:
// within chunk, 16B unit u stored at u ^ (b&7). Ping-pong on step parity.
__device__ __align__(16) __nv_bfloat16 g_hh[2][NBR*BATCH*HID];
__device__ __align__(16) __nv_bfloat16 g_hl[2][NBR*BATCH*HID];
__device__ __align__(16) float g_ys[TT*NBR*BATCH];
__device__ __align__(16) float g_xt[TT*BATCH];          // x transposed: [t][b]
__device__ unsigned g_bar[NBR*32];                      // per-branch barrier counters (padded)
// Whh bf16 hi/lo pre-swizzled tiles: [split][n][jt][kchunk][row*8 + physunit]
__device__ __align__(16) uint4 g_wimg[2][NBR][16][8][1024];

// ---------------- helpers ----------------
__device__ __forceinline__ float sigm(float x)  { return 1.0f / (1.0f + __expf(-x)); }
__device__ __forceinline__ float tanh_(float x) { return 2.0f / (1.0f + __expf(-2.0f * x)) - 1.0f; }

__device__ __forceinline__ uint32_t smem_u32(const void* p) {
    uint32_t a;
    asm("{ .reg .u64 t; cvta.to.shared.u64 t, %1; cvt.u32.u64 %0, t; }" : "=r"(a) : "l"(p));
    return a;
}
__device__ __forceinline__ void cp16(uint32_t dst, const void* src) {
    asm volatile("cp.async.cg.shared.global [%0], [%1], 16;" :: "r"(dst), "l"(src) : "memory");
}
#define CP_COMMIT() asm volatile("cp.async.commit_group;" ::: "memory")
#define CP_WAIT(N)  asm volatile("cp.async.wait_group %0;" :: "n"(N) : "memory")

__device__ __forceinline__ void ldsm4(unsigned* r, uint32_t addr) {
    asm volatile("ldmatrix.sync.aligned.m8n8.x4.shared.b16 {%0,%1,%2,%3}, [%4];"
        : "=r"(r[0]), "=r"(r[1]), "=r"(r[2]), "=r"(r[3]) : "r"(addr));
}
__device__ __forceinline__ void mma16816(float* d, const unsigned* a, const unsigned* b) {
    asm volatile("mma.sync.aligned.m16n8k16.row.col.f32.bf16.bf16.f32 "
        "{%0,%1,%2,%3}, {%4,%5,%6,%7}, {%8,%9}, {%0,%1,%2,%3};"
        : "+f"(d[0]), "+f"(d[1]), "+f"(d[2]), "+f"(d[3])
        : "r"(a[0]), "r"(a[1]), "r"(a[2]), "r"(a[3]), "r"(b[0]), "r"(b[1]));
}
__device__ __forceinline__ void split2(float w0, float w1, unsigned& hi, unsigned& lo) {
    __nv_bfloat16 h0 = __float2bfloat16_rn(w0);
    __nv_bfloat16 h1 = __float2bfloat16_rn(w1);
    __nv_bfloat16 l0 = __float2bfloat16_rn(w0 - __bfloat162float(h0));
    __nv_bfloat16 l1 = __float2bfloat16_rn(w1 - __bfloat162float(h1));
    hi = (unsigned)__bfloat16_as_ushort(h0) | ((unsigned)__bfloat16_as_ushort(h1) << 16);
    lo = (unsigned)__bfloat16_as_ushort(l0) | ((unsigned)__bfloat16_as_ushort(l1) << 16);
}

// ---------------- SMEM layout ----------------
// 3 stages at s*65536: Ah 16K | Al 16K | Bh 16K | Bl 16K  (192K total)
#define OFF_X     196608      // 512 B (x_t per batch col)
#define OFF_WB    197120      // float2[128]: (Wih, bias) per gate-row (1 KB)
#define OFF_H     198144      // float[32][132] h staging = 16896 B
#define DSMEM_REQ (215040 + 1024)

// ---------------- prep: split+swizzle Whh tiles ----------------
__global__ void prep_w_kernel(const float* __restrict__ Whh) {
    unsigned i = blockIdx.x * blockDim.x + threadIdx.x;   // 2^20
    unsigned u = i & 7, row = (i >> 3) & 127, kc = (i >> 10) & 7;
    unsigned jt = (i >> 13) & 15, n = i >> 17;
    unsigned gate = row >> 5, jj = row & 31;
    const float* src = Whh + ((size_t)(n * G4 + gate * HID + jt * 32 + jj)) * HID + kc * 64 + u * 8;
    float4 a = *(const float4*)src, b = *(const float4*)(src + 4);
    float w[8] = {a.x, a.y, a.z, a.w, b.x, b.y, b.z, b.w};
    unsigned hi[4], lo[4];
    #pragma unroll
    for (int m = 0; m < 4; m++) split2(w[2*m], w[2*m+1], hi[m], lo[m]);
    unsigned phys = u ^ (row & 7);
    g_wimg[0][n][jt][kc][row * 8 + phys] = make_uint4(hi[0], hi[1], hi[2], hi[3]);
    g_wimg[1][n][jt][kc][row * 8 + phys] = make_uint4(lo[0], lo[1], lo[2], lo[3]);
}

// ---------------- prep: h0 split+swizzle, barrier reset ----------------
__global__ void prep_h_kernel(const float* __restrict__ hn0) {
    unsigned i = blockIdx.x * blockDim.x + threadIdx.x;   // 65536
    unsigned ug = i & 63, b = (i >> 6) & 127, n = i >> 13;
    const float* src = hn0 + ((size_t)(n * 128 + b)) * 512 + ug * 8;
    unsigned hi[4], lo[4];
    #pragma unroll
    for (int m = 0; m < 4; m++) split2(src[2*m], src[2*m+1], hi[m], lo[m]);
    unsigned chunk = ug >> 3, ul = ug & 7, phys = ul ^ (b & 7);
    size_t idx = ((size_t)(n * 128 + b)) * 64 + chunk * 8 + phys;
    ((uint4*)g_hh[0])[idx] = make_uint4(hi[0], hi[1], hi[2], hi[3]);
    ((uint4*)g_hl[0])[idx] = make_uint4(lo[0], lo[1], lo[2], lo[3]);
    if (i < NBR * 32) g_bar[i] = 0;
}

// ---------------- prep: transpose x ----------------
__global__ void prep_x_kernel(const float* __restrict__ cin) {
    unsigned i = blockIdx.x * blockDim.x + threadIdx.x;   // 32768
    unsigned b = i & 127, t = i >> 7;
    g_xt[t * BATCH + b] = cin[b * TT + t];
}

// ---------------- cp.async issue helpers ----------------
__device__ __forceinline__ void issue_W(uint32_t dst, const uint4* srcA0, const uint4* srcA1,
                                        int kc, int tid) {
    #pragma unroll
    for (int r = 0; r < 4; r++) {
        int i = r * 256 + tid;
        cp16(dst + i * 16,         srcA0 + kc * 1024 + i);
        cp16(dst + 16384 + i * 16, srcA1 + kc * 1024 + i);
    }
}
__device__ __forceinline__ void issue_B(uint32_t dst, const uint4* srcBh, const uint4* srcBl,
                                        int kc, int tid) {
    #pragma unroll
    for (int r = 0; r < 4; r++) {
        int i = r * 256 + tid;
        int b_ = i >> 3, u = i & 7;
        cp16(dst + 32768 + i * 16, srcBh + b_ * 64 + kc * 8 + u);
        cp16(dst + 49152 + i * 16, srcBl + b_ * 64 + kc * 8 + u);
    }
}

// ---------------- persistent kernel: all 256 LSTM steps ----------------
// grid 128 = n*16 + jt. 256 threads / 8 warps; warp = 16-batch-col slice, M = all 128 rows.
__global__ __launch_bounds__(256, 1)
void steps_kernel(const float* __restrict__ Wih, const float* __restrict__ b_ih,
                  const float* __restrict__ b_hh)
{
    extern __shared__ __align__(16) unsigned char smem_raw[];
    uint32_t sb = smem_u32(smem_raw);
    uint32_t base = (sb + 1023) & ~1023u;
    unsigned char* bp = smem_raw + (base - sb);

    const int tid = threadIdx.x, wid = tid >> 5, lane = tid & 31;
    const int n = blockIdx.x >> 4, jt = blockIdx.x & 15;
    const int wq = wid;                    // batch-col slice [wq*16, wq*16+16)

    float*  smx  = (float*)(bp + OFF_X);
    float2* smwb = (float2*)(bp + OFF_WB);
    float*  smh  = (float*)(bp + OFF_H);

    // stage epilogue constants: (Wih, bias) per gate-row
    if (tid < 128) {
        int gg = tid >> 5, jj = tid & 31;
        int row = n * G4 + gg * HID + jt * 32 + jj;
        smwb[tid] = make_float2(Wih[row], b_ih[row] + b_hh[row]);
    }

    // cell state: fully register-resident. creg[jslot][nt][cp]
    float creg[4][2][2];
    #pragma unroll
    for (int a0 = 0; a0 < 4; a0++)
        #pragma unroll
        for (int a1 = 0; a1 < 2; a1++) { creg[a0][a1][0] = 0.0f; creg[a0][a1][1] = 0.0f; }

    // lane-derived fragment addressing
    const int aro = lane & 15;             // A: row within m16 tile
    const int auh = lane >> 4;             // A: k-unit half
    const int bro = (lane & 7) + ((lane >> 4) & 1) * 8;
    const int buh = (lane >> 3) & 1;

    const uint4* srcA0 = &g_wimg[0][n][jt][0][0];
    const uint4* srcA1 = &g_wimg[1][n][jt][0][0];

    // prologue: chunks 0,1 (W+B) into stages 0,1
    {
        const uint4* sBh = (const uint4*)g_hh[0] + (size_t)n * BATCH * 64;
        const uint4* sBl = (const uint4*)g_hl[0] + (size_t)n * BATCH * 64;
        issue_W(base, srcA0, srcA1, 0, tid);
        issue_B(base, sBh, sBl, 0, tid);
        CP_COMMIT();
        issue_W(base + 65536, srcA0, srcA1, 1, tid);
        issue_B(base + 65536, sBh, sBl, 1, tid);
        CP_COMMIT();
    }

    int stg = 0;   // stage of current chunk (advances mod 3, continuous across steps)

    for (int t = 0; t < TT; t++) {
        const int s = t & 1, dd = s ^ 1;
        const uint4* srcBh = (const uint4*)g_hh[s] + (size_t)n * BATCH * 64;
        const uint4* srcBl = (const uint4*)g_hl[s] + (size_t)n * BATCH * 64;

        if (tid < 128) smx[tid] = g_xt[t * BATCH + tid];

        float acc[8][2][4];
        #pragma unroll
        for (int a0 = 0; a0 < 8; a0++)
            #pragma unroll
            for (int a1 = 0; a1 < 2; a1++)
                #pragma unroll
                for (int a2 = 0; a2 < 4; a2++) acc[a0][a1][a2] = 0.0f;

        #pragma unroll 1
        for (int kc = 0; kc < 8; kc++) {
            CP_WAIT(1);
            __syncthreads();

            int istg = stg + 2; if (istg >= 3) istg -= 3;
            uint32_t dst = base + (uint32_t)istg * 65536u;
            if (kc < 6) {
                issue_W(dst, srcA0, srcA1, kc + 2, tid);
                issue_B(dst, srcBh, srcBl, kc + 2, tid);
                CP_COMMIT();
            } else if (t < TT - 1 || kc == 6) {
                issue_W(dst, srcA0, srcA1, kc - 6, tid);   // next step's W chunk 0/1
                CP_COMMIT();
            }

            const uint32_t tb = base + (uint32_t)stg * 65536u;
            #pragma unroll
            for (int ks = 0; ks < 4; ks++) {
                unsigned Bh[4], Bl[4];
                {
                    int rowb = wq * 16 + bro;
                    int u = ks * 2 + buh;
                    uint32_t ad = tb + 32768 + rowb * 128 + ((u ^ (rowb & 7)) << 4);
                    ldsm4(Bh, ad);
                    ldsm4(Bl, ad + 16384);
                }
                unsigned Ah[8][4], Al[8][4];
                #pragma unroll
                for (int mt = 0; mt < 8; mt++) {
                    int rowa = mt * 16 + aro;
                    int u = ks * 2 + auh;
                    uint32_t ad = tb + rowa * 128 + ((u ^ (rowa & 7)) << 4);
                    ldsm4(Ah[mt], ad);
                    ldsm4(Al[mt], ad + 16384);
                }
                // product-major order: same-acc reuse distance = 16 MMAs
                #pragma unroll
                for (int mt = 0; mt < 8; mt++)
                    #pragma unroll
                    for (int nt = 0; nt < 2; nt++)
                        mma16816(acc[mt][nt], Ah[mt], &Bh[nt * 2]);
                #pragma unroll
                for (int mt = 0; mt < 8; mt++)
                    #pragma unroll
                    for (int nt = 0; nt < 2; nt++)
                        mma16816(acc[mt][nt], Ah[mt], &Bl[nt * 2]);
                #pragma unroll
                for (int mt = 0; mt < 8; mt++)
                    #pragma unroll
                    for (int nt = 0; nt < 2; nt++)
                        mma16816(acc[mt][nt], Al[mt], &Bh[nt * 2]);
            }
            stg = (stg + 1 == 3) ? 0 : stg + 1;
        }

        // ---- epilogue: gates + cell update entirely in registers ----
        float xc[2][2];
        #pragma unroll
        for (int nt = 0; nt < 2; nt++) {
            int col0 = wq * 16 + nt * 8 + (lane & 3) * 2;
            xc[nt][0] = smx[col0];
            xc[nt][1] = smx[col0 + 1];
        }
        #pragma unroll
        for (int jslot = 0; jslot < 4; jslot++) {
            const int mtb = jslot >> 1, dh = jslot & 1;
            const int jj = mtb * 16 + (lane >> 2) + dh * 8;
            float2 wbi = smwb[jj];
            float2 wbf = smwb[32 + jj];
            float2 wbg = smwb[64 + jj];
            float2 wbo = smwb[96 + jj];
            #pragma unroll
            for (int nt = 0; nt < 2; nt++) {
                float hv[2];
                #pragma unroll
                for (int cp = 0; cp < 2; cp++) {
                    int di = dh * 2 + cp;
                    float gi = acc[mtb][nt][di]     + xc[nt][cp] * wbi.x + wbi.y;
                    float gf = acc[2 + mtb][nt][di] + xc[nt][cp] * wbf.x + wbf.y;
                    float gG = acc[4 + mtb][nt][di] + xc[nt][cp] * wbg.x + wbg.y;
                    float go = acc[6 + mtb][nt][di] + xc[nt][cp] * wbo.x + wbo.y;
                    float cn = sigm(gf) * creg[jslot][nt][cp] + sigm(gi) * tanh_(gG);
                    creg[jslot][nt][cp] = cn;
                    hv[cp] = sigm(go) * tanh_(cn);
                }
                int col0 = wq * 16 + nt * 8 + (lane & 3) * 2;
                *(float2*)&smh[jj * 132 + col0] = make_float2(hv[0], hv[1]);
            }
        }
        __syncthreads();

        // ---- h writeout: split to bf16 hi/lo, swizzle, store ----
        {
            const int b = tid & 127, half = tid >> 7;
            const int j0 = half * 16;
            unsigned ph[8], pl[8];
            float hlast = 0.0f;
            #pragma unroll
            for (int q = 0; q < 16; q++) {
                float h = smh[(j0 + q) * 132 + b];
                hlast = h;
                __nv_bfloat16 bhf = __float2bfloat16_rn(h);
                __nv_bfloat16 blf = __float2bfloat16_rn(h - __bfloat162float(bhf));
                unsigned uh = __bfloat16_as_ushort(bhf), ulw = __bfloat16_as_ushort(blf);
                if (q & 1) { ph[q >> 1] |= uh << 16; pl[q >> 1] |= ulw << 16; }
                else       { ph[q >> 1]  = uh;       pl[q >> 1]  = ulw;       }
            }
            int uq0 = jt * 4 + half * 2;
            int chunk = uq0 >> 3;
            int ul0 = uq0 & 7, ul1 = (uq0 + 1) & 7;
            int bx = b & 7;
            size_t rowbase = ((size_t)n * BATCH + b) * 64 + chunk * 8;
            uint4* oh = (uint4*)g_hh[dd];
            uint4* ol = (uint4*)g_hl[dd];
            oh[rowbase + (ul0 ^ bx)] = make_uint4(ph[0], ph[1], ph[2], ph[3]);
            oh[rowbase + (ul1 ^ bx)] = make_uint4(ph[4], ph[5], ph[6], ph[7]);
            ol[rowbase + (ul0 ^ bx)] = make_uint4(pl[0], pl[1], pl[2], pl[3]);
            ol[rowbase + (ul1 ^ bx)] = make_uint4(pl[4], pl[5], pl[6], pl[7]);
            if (jt == 15 && half == 1)
                g_ys[(size_t)t * NBR * BATCH + n * BATCH + b] = hlast;
        }
        __syncthreads();

        // ---- per-branch barrier (16 CTAs), then issue next step's B chunks 0,1 ----
        if (t < TT - 1) {
            if (tid == 0) {
                __threadfence();
                atomicAdd(&g_bar[n * 32], 1u);
                const unsigned tgt = 16u * (unsigned)(t + 1);
                unsigned v;
                do {
                    asm volatile("ld.acquire.gpu.global.u32 %0, [%1];"
                        : "=r"(v) : "l"(g_bar + n * 32) : "memory");
                } while (v < tgt);
            }
            __syncthreads();
            const uint4* nBh = (const uint4*)g_hh[dd] + (size_t)n * BATCH * 64;
            const uint4* nBl = (const uint4*)g_hl[dd] + (size_t)n * BATCH * 64;
            issue_B(base + (uint32_t)stg * 65536u, nBh, nBl, 0, tid);
            CP_COMMIT();
            int st1 = (stg + 1 == 3) ? 0 : stg + 1;
            issue_B(base + (uint32_t)st1 * 65536u, nBh, nBl, 1, tid);
            CP_COMMIT();
        }
    }
    CP_WAIT(0);
    __syncthreads();
}

// ---------------- readout ----------------
__global__ void final_kernel(const float* __restrict__ x, const float* __restrict__ Wl,
                             const float* __restrict__ bl, float* __restrict__ out)
{
    __shared__ float red[TT];
    const int b = blockIdx.x;
    const int t = threadIdx.x;
    float r = 0.0f;
    #pragma unroll
    for (int nn = 0; nn < NBR; nn++)
        r += g_ys[(size_t)t * NBR * BATCH + nn * BATCH + b] * x[(nn * BATCH + b) * TT + t];
    for (int k = 0; k < NBR; k++) {
        red[t] = r * Wl[k * TT + t];
        __syncthreads();
        for (int sft = TT / 2; sft > 0; sft >>= 1) {
            if (t < sft) red[t] += red[t + sft];
            __syncthreads();
        }
        if (t == 0) out[b * NBR + k] = red[0] + bl[k];
        __syncthreads();
    }
}

// ---------------- launch ----------------
extern "C" void kernel_launch(void* const* d_in, const int* in_sizes, int n_in,
                              void* d_out, int out_size)
{
    (void)in_sizes; (void)n_in; (void)out_size;
    const float* x    = (const float*)d_in[0];
    const float* c    = (const float*)d_in[1];
    const float* Wih  = (const float*)d_in[2];
    const float* Whh  = (const float*)d_in[3];
    const float* b_ih = (const float*)d_in[4];
    const float* b_hh = (const float*)d_in[5];
    const float* hn0  = (const float*)d_in[6];
    const float* Wl   = (const float*)d_in[7];
    const float* bl   = (const float*)d_in[8];
    float* out = (float*)d_out;

    static bool attr_set = false;
    if (!attr_set) {
        cudaFuncSetAttribute(steps_kernel, cudaFuncAttributeMaxDynamicSharedMemorySize, DSMEM_REQ);
        attr_set = true;
    }

    prep_w_kernel<<<4096, 256>>>(Whh);
    prep_h_kernel<<<256, 256>>>(hn0);
    prep_x_kernel<<<128, 256>>>(c);
    steps_kernel<<<128, 256, DSMEM_REQ>>>(Wih, b_ih, b_hh);
    final_kernel<<<BATCH, TT>>>(x, Wl, bl, out);
}

// round 12
// speedup vs baseline: 2.7285x; 1.0568x over previous
#include <cuda_runtime.h>
#include <cstdint>

#define NBR    8
#define BATCH  128
#define HID    512
#define TT     256
#define G4     2048

// ---------------- device scratch (static, no runtime alloc) ----------------
// h state, tf32 bits, packed for B-fragment LDS.64:
// g_ht[s][n][idx][colp] = {h[k][b], h[k+4][b]},  idx = (k>>3)*4 + (k&3),
// colp = b ^ ((idx&3)<<2)   (32B-granule xor swizzle, baked into gmem)
__device__ __align__(16) float2 g_ht[2][NBR][256][128];
__device__ __align__(16) float g_ys[TT*NBR*BATCH];
__device__ __align__(16) float g_xt[TT*BATCH];          // x transposed: [t][b]
__device__ unsigned g_bar[NBR*32];
// Whh tf32, packed A-fragment layout (gate-interleaved row permutation):
// per (n,jt,kc): [kb 8][mt 8][slot 32] uint4; slot=lane; row' = mt*16 + (g<<2) + (jj&3)
__device__ __align__(16) uint4 g_wimg[NBR][16][8][2048];

// ---------------- helpers ----------------
__device__ __forceinline__ float sigm(float x)  { return 1.0f / (1.0f + __expf(-x)); }
__device__ __forceinline__ float tanh_(float x) { return 2.0f / (1.0f + __expf(-2.0f * x)) - 1.0f; }

__device__ __forceinline__ uint32_t smem_u32(const void* p) {
    uint32_t a;
    asm("{ .reg .u64 t; cvta.to.shared.u64 t, %1; cvt.u32.u64 %0, t; }" : "=r"(a) : "l"(p));
    return a;
}
__device__ __forceinline__ uint32_t f2tf(float f) {
    uint32_t u; asm("cvt.rna.tf32.f32 %0, %1;" : "=r"(u) : "f"(f)); return u;
}
__device__ __forceinline__ void cp16(uint32_t dst, const void* src) {
    asm volatile("cp.async.cg.shared.global [%0], [%1], 16;" :: "r"(dst), "l"(src) : "memory");
}
#define CP_COMMIT() asm volatile("cp.async.commit_group;" ::: "memory")
#define CP_WAIT(N)  asm volatile("cp.async.wait_group %0;" :: "n"(N) : "memory")

__device__ __forceinline__ void mma_tf32(float* d, const uint32_t* a, const uint32_t* b) {
    asm volatile("mma.sync.aligned.m16n8k8.row.col.f32.tf32.tf32.f32 "
        "{%0,%1,%2,%3}, {%4,%5,%6,%7}, {%8,%9}, {%0,%1,%2,%3};"
        : "+f"(d[0]), "+f"(d[1]), "+f"(d[2]), "+f"(d[3])
        : "r"(a[0]), "r"(a[1]), "r"(a[2]), "r"(a[3]), "r"(b[0]), "r"(b[1]));
}

// ---------------- SMEM layout ----------------
// 3 stages at s*65536: A 32K | B 32K
#define OFF_B   32768
#define OFF_X   196608        // 512 B
#define OFF_WB  197120        // float2[128]
#define OFF_H   198144        // float[32][132] = 16896 B
#define DSMEM_REQ 216064

// ---------------- prep: Whh -> tf32, permuted, fragment-packed ----------------
__global__ void prep_w_kernel(const float* __restrict__ Whh) {
    unsigned i = blockIdx.x * blockDim.x + threadIdx.x;   // 2^20
    unsigned sfull = i & 15, mt = (i >> 4) & 7, kb = (i >> 7) & 7;
    unsigned kc = (i >> 10) & 7, jt = (i >> 13) & 15, n = i >> 17;
    unsigned g = sfull >> 2, jj = mt * 4 + (sfull & 3);
    const float* src = Whh + ((size_t)(n * G4 + g * HID + jt * 32 + jj)) * HID + kc * 64 + kb * 8;
    uint32_t* dst = (uint32_t*)&g_wimg[n][jt][kc][0];
    unsigned r8 = sfull & 7, hb = sfull >> 3;
    #pragma unroll
    for (int c = 0; c < 8; c++) {
        uint32_t v = f2tf(src[c]);
        dst[(((kb * 8 + mt) * 32) + r8 * 4 + (c & 3)) * 4 + hb + 2 * (c >> 2)] = v;
    }
}

// ---------------- prep: h0 -> tf32 packed, barrier reset ----------------
__global__ void prep_h_kernel(const float* __restrict__ hn0) {
    unsigned i = blockIdx.x * blockDim.x + threadIdx.x;   // 262144
    unsigned b = i & 127, idx = (i >> 7) & 255, n = i >> 15;
    unsigned k = (idx >> 2) * 8 + (idx & 3);
    float h0 = hn0[((size_t)(n * 128 + b)) * 512 + k];
    float h1 = hn0[((size_t)(n * 128 + b)) * 512 + k + 4];
    float2 v; ((uint32_t*)&v)[0] = f2tf(h0); ((uint32_t*)&v)[1] = f2tf(h1);
    g_ht[0][n][idx][b ^ ((idx & 3) << 2)] = v;
    if (i < NBR * 32) g_bar[i] = 0;
}

// ---------------- prep: transpose x ----------------
__global__ void prep_x_kernel(const float* __restrict__ cin) {
    unsigned i = blockIdx.x * blockDim.x + threadIdx.x;   // 32768
    unsigned b = i & 127, t = i >> 7;
    g_xt[t * BATCH + b] = cin[b * TT + t];
}

// ---------------- cp.async issue helpers (2048 x 16B each) ----------------
__device__ __forceinline__ void issue_W(uint32_t dst, const uint4* srcW, int kc, int tid) {
    #pragma unroll
    for (int r = 0; r < 8; r++) {
        int i = r * 256 + tid;
        cp16(dst + i * 16, srcW + kc * 2048 + i);
    }
}
__device__ __forceinline__ void issue_B(uint32_t dst, const uint4* srcB, int kc, int tid) {
    #pragma unroll
    for (int r = 0; r < 8; r++) {
        int i = r * 256 + tid;
        cp16(dst + OFF_B + i * 16, srcB + kc * 2048 + i);
    }
}

// ---------------- persistent kernel: all 256 LSTM steps ----------------
// grid 128 = n*16 + jt. 8 warps: wm = wid&3 (m-slice, mt = wm*2..+1), wb = wid>>2 (batch half).
__global__ __launch_bounds__(256, 1)
void steps_kernel(const float* __restrict__ Wih, const float* __restrict__ b_ih,
                  const float* __restrict__ b_hh)
{
    extern __shared__ __align__(16) unsigned char smem_raw[];
    uint32_t sb = smem_u32(smem_raw);
    uint32_t base = (sb + 1023) & ~1023u;
    unsigned char* bp = smem_raw + (base - sb);

    const int tid = threadIdx.x, wid = tid >> 5, lane = tid & 31;
    const int n = blockIdx.x >> 4, jt = blockIdx.x & 15;
    const int wm = wid & 3, wb = wid >> 2;
    const int q = lane >> 2, lr = lane & 3;

    float*  smx  = (float*)(bp + OFF_X);
    float2* smwb = (float2*)(bp + OFF_WB);
    float*  smh  = (float*)(bp + OFF_H);

    if (tid < 128) {
        int gg = tid >> 5, jj = tid & 31;
        int row = n * G4 + gg * HID + jt * 32 + jj;
        smwb[tid] = make_float2(Wih[row], b_ih[row] + b_hh[row]);
    }
    __syncthreads();

    // per-thread gate constants (gates gA = q>>2 in {0,1} and gA+2)
    const int gA = q >> 2;
    float2 wbA[2], wbB[2];
    #pragma unroll
    for (int m2 = 0; m2 < 2; m2++) {
        int jj = (wm * 2 + m2) * 4 + (q & 3);
        wbA[m2] = smwb[gA * 32 + jj];
        wbB[m2] = smwb[(gA + 2) * 32 + jj];
    }

    // register-resident cell state (valid on lanes >= 16)
    float creg[2][8][2];
    #pragma unroll
    for (int a = 0; a < 2; a++)
        #pragma unroll
        for (int b2 = 0; b2 < 8; b2++) { creg[a][b2][0] = 0.0f; creg[a][b2][1] = 0.0f; }

    const uint4* srcW = &g_wimg[n][jt][0][0];

    // prologue: chunks 0,1 -> stages 0,1
    {
        const uint4* sB = (const uint4*)&g_ht[0][n][0][0];
        issue_W(base, srcW, 0, tid);
        issue_B(base, sB, 0, tid);
        CP_COMMIT();
        issue_W(base + 65536, srcW, 1, tid);
        issue_B(base + 65536, sB, 1, tid);
        CP_COMMIT();
    }

    int stg = 0;

    #pragma unroll 1
    for (int t = 0; t < TT; t++) {
        const int s = t & 1, dd = s ^ 1;
        const uint4* srcB = (const uint4*)&g_ht[s][n][0][0];

        if (tid < 128) smx[tid] = g_xt[t * BATCH + tid];

        float acc[2][8][4];
        #pragma unroll
        for (int a0 = 0; a0 < 2; a0++)
            #pragma unroll
            for (int a1 = 0; a1 < 8; a1++)
                #pragma unroll
                for (int a2 = 0; a2 < 4; a2++) acc[a0][a1][a2] = 0.0f;

        #pragma unroll 1
        for (int kc = 0; kc < 8; kc++) {
            CP_WAIT(1);
            __syncthreads();

            int istg = stg + 2; if (istg >= 3) istg -= 3;
            uint32_t dst = base + (uint32_t)istg * 65536u;
            if (kc < 6) {
                issue_W(dst, srcW, kc + 2, tid);
                issue_B(dst, srcB, kc + 2, tid);
                CP_COMMIT();
            } else if (t < TT - 1 || kc == 6) {
                issue_W(dst, srcW, kc - 6, tid);    // next step's W chunk 0/1
                CP_COMMIT();
            }

            const uint32_t tb = base + (uint32_t)stg * 65536u;
            #pragma unroll
            for (int kb = 0; kb < 8; kb++) {
                uint32_t Af[2][4];
                #pragma unroll
                for (int m2 = 0; m2 < 2; m2++) {
                    uint32_t ad = tb + (uint32_t)(((kb * 8 + (wm * 2 + m2)) * 32 + lane) * 16);
                    asm volatile("ld.shared.v4.b32 {%0,%1,%2,%3}, [%4];"
                        : "=r"(Af[m2][0]), "=r"(Af[m2][1]), "=r"(Af[m2][2]), "=r"(Af[m2][3])
                        : "r"(ad));
                }
                uint32_t Bf[8][2];
                #pragma unroll
                for (int nt = 0; nt < 8; nt++) {
                    int colp = (wb * 64 + nt * 8 + q) ^ (lr << 2);
                    uint32_t ad = tb + OFF_B + (uint32_t)((kb * 4 + lr) * 1024 + colp * 8);
                    asm volatile("ld.shared.v2.b32 {%0,%1}, [%2];"
                        : "=r"(Bf[nt][0]), "=r"(Bf[nt][1]) : "r"(ad));
                }
                #pragma unroll
                for (int m2 = 0; m2 < 2; m2++)
                    #pragma unroll
                    for (int nt = 0; nt < 8; nt++)
                        mma_tf32(acc[m2][nt], Af[m2], Bf[nt]);
            }
            stg = (stg + 1 == 3) ? 0 : stg + 1;
        }

        // ---- epilogue: gates in regs, shfl pair (i,g)<->(f,o), cell in regs ----
        float xc[8][2];
        #pragma unroll
        for (int nt = 0; nt < 8; nt++) {
            int col = wb * 64 + nt * 8 + lr * 2;
            xc[nt][0] = smx[col]; xc[nt][1] = smx[col + 1];
        }
        #pragma unroll
        for (int m2 = 0; m2 < 2; m2++) {
            #pragma unroll
            for (int nt = 0; nt < 8; nt++) {
                float hv[2];
                #pragma unroll
                for (int cp = 0; cp < 2; cp++) {
                    float v0 = acc[m2][nt][cp]     + xc[nt][cp] * wbA[m2].x + wbA[m2].y;
                    float v1 = acc[m2][nt][2 + cp] + xc[nt][cp] * wbB[m2].x + wbB[m2].y;
                    float sv0 = sigm(v0);                      // sigm(i) | sigm(f)
                    float a1 = (lane < 16) ? (-2.0f * v1) : (-v1);
                    float e1 = __expf(a1);
                    float w1 = (lane < 16) ? (2.0f / (1.0f + e1) - 1.0f)   // tanh(g)
                                           : (1.0f / (1.0f + e1));          // sigm(o)
                    float pv = sv0 * w1;                        // lanes<16: sigm(i)*tanh(g)
                    float rcv = __shfl_xor_sync(0xffffffffu, pv, 16);
                    float cn = sv0 * creg[m2][nt][cp] + rcv;    // lanes>=16 valid
                    creg[m2][nt][cp] = cn;
                    hv[cp] = w1 * tanh_(cn);                    // lanes>=16: sigm(o)*tanh(cn)
                }
                if (lane >= 16) {
                    int jj = (wm * 2 + m2) * 4 + (q & 3);
                    int col = wb * 64 + nt * 8 + lr * 2;
                    *(float2*)&smh[jj * 132 + col] = make_float2(hv[0], hv[1]);
                }
            }
        }
        __syncthreads();

        // ---- h writeout: tf32-pack into g_ht[dd] (B-fragment gmem layout) ----
        #pragma unroll
        for (int w8 = 0; w8 < 8; w8++) {
            int id = w8 * 256 + tid;            // 0..2047
            int il = id >> 7;                   // idx_local 0..15
            int b  = id & 127;
            int r  = il & 3;
            int j0 = (il >> 2) * 8 + r;
            float h0 = smh[j0 * 132 + b];
            float h1 = smh[(j0 + 4) * 132 + b];
            float2 v; ((uint32_t*)&v)[0] = f2tf(h0); ((uint32_t*)&v)[1] = f2tf(h1);
            g_ht[dd][n][jt * 16 + il][b ^ (r << 2)] = v;
            if (jt == 15 && il == 15)
                g_ys[(size_t)t * NBR * BATCH + n * BATCH + b] = h1;   // h[j=511]
        }
        __syncthreads();

        // ---- per-branch barrier (16 CTAs), then next step's B chunks 0,1 ----
        if (t < TT - 1) {
            if (tid == 0) {
                __threadfence();
                atomicAdd(&g_bar[n * 32], 1u);
                const unsigned tgt = 16u * (unsigned)(t + 1);
                unsigned v;
                do {
                    asm volatile("ld.acquire.gpu.global.u32 %0, [%1];"
                        : "=r"(v) : "l"(g_bar + n * 32) : "memory");
                } while (v < tgt);
            }
            __syncthreads();
            const uint4* nB = (const uint4*)&g_ht[dd][n][0][0];
            issue_B(base + (uint32_t)stg * 65536u, nB, 0, tid);
            CP_COMMIT();
            int st1 = (stg + 1 == 3) ? 0 : stg + 1;
            issue_B(base + (uint32_t)st1 * 65536u, nB, 1, tid);
            CP_COMMIT();
        }
    }
    CP_WAIT(0);
    __syncthreads();
}

// ---------------- readout ----------------
__global__ void final_kernel(const float* __restrict__ x, const float* __restrict__ Wl,
                             const float* __restrict__ bl, float* __restrict__ out)
{
    __shared__ float red[TT];
    const int b = blockIdx.x;
    const int t = threadIdx.x;
    float r = 0.0f;
    #pragma unroll
    for (int nn = 0; nn < NBR; nn++)
        r += g_ys[(size_t)t * NBR * BATCH + nn * BATCH + b] * x[(nn * BATCH + b) * TT + t];
    for (int k = 0; k < NBR; k++) {
        red[t] = r * Wl[k * TT + t];
        __syncthreads();
        for (int sft = TT / 2; sft > 0; sft >>= 1) {
            if (t < sft) red[t] += red[t + sft];
            __syncthreads();
        }
        if (t == 0) out[b * NBR + k] = red[0] + bl[k];
        __syncthreads();
    }
}

// ---------------- launch ----------------
extern "C" void kernel_launch(void* const* d_in, const int* in_sizes, int n_in,
                              void* d_out, int out_size)
{
    (void)in_sizes; (void)n_in; (void)out_size;
    const float* x    = (const float*)d_in[0];
    const float* c    = (const float*)d_in[1];
    const float* Wih  = (const float*)d_in[2];
    const float* Whh  = (const float*)d_in[3];
    const float* b_ih = (const float*)d_in[4];
    const float* b_hh = (const float*)d_in[5];
    const float* hn0  = (const float*)d_in[6];
    const float* Wl   = (const float*)d_in[7];
    const float* bl   = (const float*)d_in[8];
    float* out = (float*)d_out;

    static bool attr_set = false;
    if (!attr_set) {
        cudaFuncSetAttribute(steps_kernel, cudaFuncAttributeMaxDynamicSharedMemorySize, DSMEM_REQ);
        attr_set = true;
    }

    prep_w_kernel<<<4096, 256>>>(Whh);
    prep_h_kernel<<<1024, 256>>>(hn0);
    prep_x_kernel<<<128, 256>>>(c);
    steps_kernel<<<128, 256, DSMEM_REQ>>>(Wih, b_ih, b_hh);
    final_kernel<<<BATCH, TT>>>(x, Wl, bl, out);
}

// round 13
// speedup vs baseline: 3.1755x; 1.1638x over previous
#include <cuda_runtime.h>
#include <cstdint>

#define NBR    8
#define BATCH  128
#define HID    512
#define TT     256
#define G4     2048
#define THREADS 512

// ---------------- device scratch (static, no runtime alloc) ----------------
// h state, tf32 bits, packed for B-fragment LDS.64:
// g_ht[s][n][idx][colp] = {h[k][b], h[k+4][b]},  idx = (k>>3)*4 + (k&3),
// colp = b ^ ((idx&3)<<2)   (32B-granule xor swizzle, baked into gmem)
__device__ __align__(16) float2 g_ht[2][NBR][256][128];
__device__ __align__(16) float g_ys[TT*NBR*BATCH];
__device__ __align__(16) float g_xt[TT*BATCH];          // x transposed: [t][b]
__device__ unsigned g_bar[NBR*32];
// Whh tf32, packed A-fragment layout (gate-interleaved row permutation):
// per (n,jt,kc): [kb 8][mt 8][slot 32] uint4; slot=lane; row' = mt*16 + (g<<2) + (jj&3)
__device__ __align__(16) uint4 g_wimg[NBR][16][8][2048];

// ---------------- helpers ----------------
__device__ __forceinline__ float sigm(float x)  { return 1.0f / (1.0f + __expf(-x)); }
__device__ __forceinline__ float tanh_(float x) { return 2.0f / (1.0f + __expf(-2.0f * x)) - 1.0f; }

__device__ __forceinline__ uint32_t smem_u32(const void* p) {
    uint32_t a;
    asm("{ .reg .u64 t; cvta.to.shared.u64 t, %1; cvt.u32.u64 %0, t; }" : "=r"(a) : "l"(p));
    return a;
}
__device__ __forceinline__ uint32_t f2tf(float f) {
    uint32_t u; asm("cvt.rna.tf32.f32 %0, %1;" : "=r"(u) : "f"(f)); return u;
}
__device__ __forceinline__ void cp16(uint32_t dst, const void* src) {
    asm volatile("cp.async.cg.shared.global [%0], [%1], 16;" :: "r"(dst), "l"(src) : "memory");
}
#define CP_COMMIT() asm volatile("cp.async.commit_group;" ::: "memory")
#define CP_WAIT(N)  asm volatile("cp.async.wait_group %0;" :: "n"(N) : "memory")

__device__ __forceinline__ void mma_tf32(float* d, const uint32_t* a, const uint32_t* b) {
    asm volatile("mma.sync.aligned.m16n8k8.row.col.f32.tf32.tf32.f32 "
        "{%0,%1,%2,%3}, {%4,%5,%6,%7}, {%8,%9}, {%0,%1,%2,%3};"
        : "+f"(d[0]), "+f"(d[1]), "+f"(d[2]), "+f"(d[3])
        : "r"(a[0]), "r"(a[1]), "r"(a[2]), "r"(a[3]), "r"(b[0]), "r"(b[1]));
}

// ---------------- SMEM layout ----------------
// 3 stages at s*65536: A 32K | B 32K
#define OFF_B   32768
#define OFF_X   196608        // 512 B
#define OFF_WB  197120        // float2[128]
#define OFF_H   198144        // float[32][132] = 16896 B
#define DSMEM_REQ 216064

// ---------------- prep: Whh -> tf32, permuted, fragment-packed ----------------
__global__ void prep_w_kernel(const float* __restrict__ Whh) {
    unsigned i = blockIdx.x * blockDim.x + threadIdx.x;   // 2^20
    unsigned sfull = i & 15, mt = (i >> 4) & 7, kb = (i >> 7) & 7;
    unsigned kc = (i >> 10) & 7, jt = (i >> 13) & 15, n = i >> 17;
    unsigned g = sfull >> 2, jj = mt * 4 + (sfull & 3);
    const float* src = Whh + ((size_t)(n * G4 + g * HID + jt * 32 + jj)) * HID + kc * 64 + kb * 8;
    uint32_t* dst = (uint32_t*)&g_wimg[n][jt][kc][0];
    unsigned r8 = sfull & 7, hb = sfull >> 3;
    #pragma unroll
    for (int c = 0; c < 8; c++) {
        uint32_t v = f2tf(src[c]);
        dst[(((kb * 8 + mt) * 32) + r8 * 4 + (c & 3)) * 4 + hb + 2 * (c >> 2)] = v;
    }
}

// ---------------- prep: h0 -> tf32 packed, barrier reset ----------------
__global__ void prep_h_kernel(const float* __restrict__ hn0) {
    unsigned i = blockIdx.x * blockDim.x + threadIdx.x;   // 262144
    unsigned b = i & 127, idx = (i >> 7) & 255, n = i >> 15;
    unsigned k = (idx >> 2) * 8 + (idx & 3);
    float h0 = hn0[((size_t)(n * 128 + b)) * 512 + k];
    float h1 = hn0[((size_t)(n * 128 + b)) * 512 + k + 4];
    float2 v; ((uint32_t*)&v)[0] = f2tf(h0); ((uint32_t*)&v)[1] = f2tf(h1);
    g_ht[0][n][idx][b ^ ((idx & 3) << 2)] = v;
    if (i < NBR * 32) g_bar[i] = 0;
}

// ---------------- prep: transpose x ----------------
__global__ void prep_x_kernel(const float* __restrict__ cin) {
    unsigned i = blockIdx.x * blockDim.x + threadIdx.x;   // 32768
    unsigned b = i & 127, t = i >> 7;
    g_xt[t * BATCH + b] = cin[b * TT + t];
}

// ---------------- cp.async issue helpers (2048 x 16B each, 512 threads) ----------------
__device__ __forceinline__ void issue_W(uint32_t dst, const uint4* srcW, int kc, int tid) {
    #pragma unroll
    for (int r = 0; r < 4; r++) {
        int i = r * THREADS + tid;
        cp16(dst + i * 16, srcW + kc * 2048 + i);
    }
}
__device__ __forceinline__ void issue_B(uint32_t dst, const uint4* srcB, int kc, int tid) {
    #pragma unroll
    for (int r = 0; r < 4; r++) {
        int i = r * THREADS + tid;
        cp16(dst + OFF_B + i * 16, srcB + kc * 2048 + i);
    }
}

// ---------------- persistent kernel: all 256 LSTM steps ----------------
// grid 128 = n*16 + jt. 16 warps: wm = wid&3 (mt = wm*2..+1), wb = wid>>2 (32-col slice).
__global__ __launch_bounds__(THREADS, 1)
void steps_kernel(const float* __restrict__ Wih, const float* __restrict__ b_ih,
                  const float* __restrict__ b_hh)
{
    extern __shared__ __align__(16) unsigned char smem_raw[];
    uint32_t sb = smem_u32(smem_raw);
    uint32_t base = (sb + 1023) & ~1023u;
    unsigned char* bp = smem_raw + (base - sb);

    const int tid = threadIdx.x, wid = tid >> 5, lane = tid & 31;
    const int n = blockIdx.x >> 4, jt = blockIdx.x & 15;
    const int wm = wid & 3, wb = wid >> 2;
    const int q = lane >> 2, lr = lane & 3;

    float*  smx  = (float*)(bp + OFF_X);
    float2* smwb = (float2*)(bp + OFF_WB);
    float*  smh  = (float*)(bp + OFF_H);

    if (tid < 128) {
        int gg = tid >> 5, jj = tid & 31;
        int row = n * G4 + gg * HID + jt * 32 + jj;
        smwb[tid] = make_float2(Wih[row], b_ih[row] + b_hh[row]);
    }
    __syncthreads();

    // per-thread gate constants (gates gA = q>>2 in {0,1} and gA+2)
    float2 wbA[2], wbB[2];
    {
        const int gA = q >> 2;
        #pragma unroll
        for (int m2 = 0; m2 < 2; m2++) {
            int jj = (wm * 2 + m2) * 4 + (q & 3);
            wbA[m2] = smwb[gA * 32 + jj];
            wbB[m2] = smwb[(gA + 2) * 32 + jj];
        }
    }

    // register-resident cell state (valid on lanes >= 16)
    float creg[2][4][2];
    #pragma unroll
    for (int a = 0; a < 2; a++)
        #pragma unroll
        for (int b2 = 0; b2 < 4; b2++) { creg[a][b2][0] = 0.0f; creg[a][b2][1] = 0.0f; }

    const uint4* srcW = &g_wimg[n][jt][0][0];

    // prologue: chunks 0,1 -> stages 0,1
    {
        const uint4* sB = (const uint4*)&g_ht[0][n][0][0];
        issue_W(base, srcW, 0, tid);
        issue_B(base, sB, 0, tid);
        CP_COMMIT();
        issue_W(base + 65536, srcW, 1, tid);
        issue_B(base + 65536, sB, 1, tid);
        CP_COMMIT();
    }

    int stg = 0;

    #pragma unroll 1
    for (int t = 0; t < TT; t++) {
        const int s = t & 1, dd = s ^ 1;
        const uint4* srcB = (const uint4*)&g_ht[s][n][0][0];

        if (tid < 128) smx[tid] = g_xt[t * BATCH + tid];

        float acc[2][4][4];
        #pragma unroll
        for (int a0 = 0; a0 < 2; a0++)
            #pragma unroll
            for (int a1 = 0; a1 < 4; a1++)
                #pragma unroll
                for (int a2 = 0; a2 < 4; a2++) acc[a0][a1][a2] = 0.0f;

        #pragma unroll 1
        for (int kc = 0; kc < 8; kc++) {
            CP_WAIT(1);
            __syncthreads();

            int istg = stg + 2; if (istg >= 3) istg -= 3;
            uint32_t dst = base + (uint32_t)istg * 65536u;
            if (kc < 6) {
                issue_W(dst, srcW, kc + 2, tid);
                issue_B(dst, srcB, kc + 2, tid);
                CP_COMMIT();
            } else if (t < TT - 1 || kc == 6) {
                issue_W(dst, srcW, kc - 6, tid);    // next step's W chunk 0/1
                CP_COMMIT();
            }

            const uint32_t tb = base + (uint32_t)stg * 65536u;
            #pragma unroll
            for (int kb = 0; kb < 8; kb++) {
                uint32_t Af[2][4];
                #pragma unroll
                for (int m2 = 0; m2 < 2; m2++) {
                    uint32_t ad = tb + (uint32_t)(((kb * 8 + (wm * 2 + m2)) * 32 + lane) * 16);
                    asm volatile("ld.shared.v4.b32 {%0,%1,%2,%3}, [%4];"
                        : "=r"(Af[m2][0]), "=r"(Af[m2][1]), "=r"(Af[m2][2]), "=r"(Af[m2][3])
                        : "r"(ad));
                }
                uint32_t Bf[4][2];
                #pragma unroll
                for (int nt = 0; nt < 4; nt++) {
                    int colp = (wb * 32 + nt * 8 + q) ^ (lr << 2);
                    uint32_t ad = tb + OFF_B + (uint32_t)((kb * 4 + lr) * 1024 + colp * 8);
                    asm volatile("ld.shared.v2.b32 {%0,%1}, [%2];"
                        : "=r"(Bf[nt][0]), "=r"(Bf[nt][1]) : "r"(ad));
                }
                #pragma unroll
                for (int m2 = 0; m2 < 2; m2++)
                    #pragma unroll
                    for (int nt = 0; nt < 4; nt++)
                        mma_tf32(acc[m2][nt], Af[m2], Bf[nt]);
            }
            stg = (stg + 1 == 3) ? 0 : stg + 1;
        }

        // ---- epilogue: gates in regs, shfl pair (i,g)<->(f,o), cell in regs ----
        #pragma unroll
        for (int m2 = 0; m2 < 2; m2++) {
            #pragma unroll
            for (int nt = 0; nt < 4; nt++) {
                int col = wb * 32 + nt * 8 + lr * 2;
                float hv[2];
                #pragma unroll
                for (int cp = 0; cp < 2; cp++) {
                    float xv = smx[col + cp];
                    float v0 = acc[m2][nt][cp]     + xv * wbA[m2].x + wbA[m2].y;
                    float v1 = acc[m2][nt][2 + cp] + xv * wbB[m2].x + wbB[m2].y;
                    float sv0 = sigm(v0);                      // sigm(i) | sigm(f)
                    float a1 = (lane < 16) ? (-2.0f * v1) : (-v1);
                    float e1 = __expf(a1);
                    float w1 = (lane < 16) ? (2.0f / (1.0f + e1) - 1.0f)   // tanh(g)
                                           : (1.0f / (1.0f + e1));          // sigm(o)
                    float pv = sv0 * w1;                        // lanes<16: sigm(i)*tanh(g)
                    float rcv = __shfl_xor_sync(0xffffffffu, pv, 16);
                    float cn = sv0 * creg[m2][nt][cp] + rcv;    // lanes>=16 valid
                    creg[m2][nt][cp] = cn;
                    hv[cp] = w1 * tanh_(cn);                    // lanes>=16: sigm(o)*tanh(cn)
                }
                if (lane >= 16) {
                    int jj = (wm * 2 + m2) * 4 + (q & 3);
                    *(float2*)&smh[jj * 132 + col] = make_float2(hv[0], hv[1]);
                }
            }
        }
        __syncthreads();

        // ---- h writeout: tf32-pack into g_ht[dd] (B-fragment gmem layout) ----
        #pragma unroll
        for (int w8 = 0; w8 < 4; w8++) {
            int id = w8 * THREADS + tid;        // 0..2047
            int il = id >> 7;                   // idx_local 0..15
            int b  = id & 127;
            int r  = il & 3;
            int j0 = (il >> 2) * 8 + r;
            float h0 = smh[j0 * 132 + b];
            float h1 = smh[(j0 + 4) * 132 + b];
            float2 v; ((uint32_t*)&v)[0] = f2tf(h0); ((uint32_t*)&v)[1] = f2tf(h1);
            g_ht[dd][n][jt * 16 + il][b ^ (r << 2)] = v;
            if (jt == 15 && il == 15)
                g_ys[(size_t)t * NBR * BATCH + n * BATCH + b] = h1;   // h[j=511]
        }
        __syncthreads();

        // ---- per-branch barrier (16 CTAs), then next step's B chunks 0,1 ----
        if (t < TT - 1) {
            if (tid == 0) {
                __threadfence();
                atomicAdd(&g_bar[n * 32], 1u);
                const unsigned tgt = 16u * (unsigned)(t + 1);
                unsigned v;
                do {
                    asm volatile("ld.acquire.gpu.global.u32 %0, [%1];"
                        : "=r"(v) : "l"(g_bar + n * 32) : "memory");
                } while (v < tgt);
            }
            __syncthreads();
            const uint4* nB = (const uint4*)&g_ht[dd][n][0][0];
            issue_B(base + (uint32_t)stg * 65536u, nB, 0, tid);
            CP_COMMIT();
            int st1 = (stg + 1 == 3) ? 0 : stg + 1;
            issue_B(base + (uint32_t)st1 * 65536u, nB, 1, tid);
            CP_COMMIT();
        }
    }
    CP_WAIT(0);
    __syncthreads();
}

// ---------------- readout ----------------
__global__ void final_kernel(const float* __restrict__ x, const float* __restrict__ Wl,
                             const float* __restrict__ bl, float* __restrict__ out)
{
    __shared__ float red[TT];
    const int b = blockIdx.x;
    const int t = threadIdx.x;
    float r = 0.0f;
    #pragma unroll
    for (int nn = 0; nn < NBR; nn++)
        r += g_ys[(size_t)t * NBR * BATCH + nn * BATCH + b] * x[(nn * BATCH + b) * TT + t];
    for (int k = 0; k < NBR; k++) {
        red[t] = r * Wl[k * TT + t];
        __syncthreads();
        for (int sft = TT / 2; sft > 0; sft >>= 1) {
            if (t < sft) red[t] += red[t + sft];
            __syncthreads();
        }
        if (t == 0) out[b * NBR + k] = red[0] + bl[k];
        __syncthreads();
    }
}

// ---------------- launch ----------------
extern "C" void kernel_launch(void* const* d_in, const int* in_sizes, int n_in,
                              void* d_out, int out_size)
{
    (void)in_sizes; (void)n_in; (void)out_size;
    const float* x    = (const float*)d_in[0];
    const float* c    = (const float*)d_in[1];
    const float* Wih  = (const float*)d_in[2];
    const float* Whh  = (const float*)d_in[3];
    const float* b_ih = (const float*)d_in[4];
    const float* b_hh = (const float*)d_in[5];
    const float* hn0  = (const float*)d_in[6];
    const float* Wl   = (const float*)d_in[7];
    const float* bl   = (const float*)d_in[8];
    float* out = (float*)d_out;

    static bool attr_set = false;
    if (!attr_set) {
        cudaFuncSetAttribute(steps_kernel, cudaFuncAttributeMaxDynamicSharedMemorySize, DSMEM_REQ);
        attr_set = true;
    }

    prep_w_kernel<<<4096, 256>>>(Whh);
    prep_h_kernel<<<1024, 256>>>(hn0);
    prep_x_kernel<<<128, 256>>>(c);
    steps_kernel<<<128, THREADS, DSMEM_REQ>>>(Wih, b_ih, b_hh);
    final_kernel<<<BATCH, TT>>>(x, Wl, bl, out);
}

// round 14
// speedup vs baseline: 4.6001x; 1.4486x over previous
#include <cuda_runtime.h>
#include <cstdint>

#define NBR    8
#define BATCH  128
#define HID    512
#define TT     256
#define G4     2048
#define THREADS 512

// ---------------- device scratch (static, no runtime alloc) ----------------
// h state fp16, B-fragment layout: g_ht[s][n][row][colp] (uint2),
// row = kc*16 + kb*4 + kk; uint2 = {f16x2(k=2kk,2kk+1 | b), f16x2(k=2kk+8,2kk+9 | b)},
// k relative to kb16 block; colp = b ^ (kk<<2). Ping-pong on step parity.
__device__ __align__(16) uint2 g_ht[2][NBR][128][128];
__device__ __align__(16) float g_ys[TT*NBR*BATCH];
__device__ __align__(16) float g_xt[TT*BATCH];          // x transposed: [t][b]
__device__ unsigned g_bar[NBR*32];
// Whh fp16, A-fragment layout (gate-interleaved row permutation):
// per (n,jt,kc): [kb 4][mt 8][lane 32] uint4 = {a0,a1,a2,a3}
__device__ __align__(16) uint4 g_wimg[NBR][16][8][1024];

// ---------------- helpers ----------------
__device__ __forceinline__ float sigm(float x)  { return 1.0f / (1.0f + __expf(-x)); }
__device__ __forceinline__ float tanh_(float x) { return 2.0f / (1.0f + __expf(-2.0f * x)) - 1.0f; }

__device__ __forceinline__ uint32_t smem_u32(const void* p) {
    uint32_t a;
    asm("{ .reg .u64 t; cvta.to.shared.u64 t, %1; cvt.u32.u64 %0, t; }" : "=r"(a) : "l"(p));
    return a;
}
// pack two fp32 -> f16x2 {lo, hi}
__device__ __forceinline__ uint32_t packf16(float lo, float hi) {
    uint32_t r; asm("cvt.rn.f16x2.f32 %0, %1, %2;" : "=r"(r) : "f"(hi), "f"(lo)); return r;
}
__device__ __forceinline__ void cp16(uint32_t dst, const void* src) {
    asm volatile("cp.async.cg.shared.global [%0], [%1], 16;" :: "r"(dst), "l"(src) : "memory");
}
#define CP_COMMIT() asm volatile("cp.async.commit_group;" ::: "memory")
#define CP_WAIT(N)  asm volatile("cp.async.wait_group %0;" :: "n"(N) : "memory")

__device__ __forceinline__ void mma_f16(float* d, const uint32_t* a, const uint32_t* b) {
    asm volatile("mma.sync.aligned.m16n8k16.row.col.f32.f16.f16.f32 "
        "{%0,%1,%2,%3}, {%4,%5,%6,%7}, {%8,%9}, {%0,%1,%2,%3};"
        : "+f"(d[0]), "+f"(d[1]), "+f"(d[2]), "+f"(d[3])
        : "r"(a[0]), "r"(a[1]), "r"(a[2]), "r"(a[3]), "r"(b[0]), "r"(b[1]));
}

// ---------------- SMEM layout ----------------
// 3 stages at s*32768: A 16K | B 16K
#define STAGE   32768
#define OFF_B   16384
#define OFF_X   98304         // 512 B
#define OFF_WB  98816         // float2[128] = 1 KB
#define OFF_H   99840         // float[32][132] = 16896 B
#define DSMEM_REQ 117760

// ---------------- prep: Whh -> fp16 A-fragments, permuted ----------------
__global__ void prep_w_kernel(const float* __restrict__ Whh) {
    unsigned i = blockIdx.x * blockDim.x + threadIdx.x;   // 2^20
    unsigned lane = i & 31, mt = (i >> 5) & 7, kb = (i >> 8) & 3;
    unsigned kc = (i >> 10) & 7, jt = (i >> 13) & 15, n = i >> 17;
    unsigned gid = lane >> 2, tig = lane & 3;
    unsigned g0 = gid >> 2, jl = gid & 3;
    unsigned j = jt * 32 + mt * 4 + jl;
    const float* rA = Whh + ((size_t)(n * G4 + g0 * HID + j)) * HID;        // gate g0
    const float* rB = Whh + ((size_t)(n * G4 + (g0 + 2) * HID + j)) * HID;  // gate g0+2
    unsigned k0 = kc * 64 + kb * 16 + 2 * tig;
    uint4 v;
    v.x = packf16(rA[k0],     rA[k0 + 1]);
    v.y = packf16(rB[k0],     rB[k0 + 1]);
    v.z = packf16(rA[k0 + 8], rA[k0 + 9]);
    v.w = packf16(rB[k0 + 8], rB[k0 + 9]);
    g_wimg[n][jt][kc][(kb * 8 + mt) * 32 + lane] = v;
}

// ---------------- prep: h0 -> fp16 packed, barrier reset ----------------
__global__ void prep_h_kernel(const float* __restrict__ hn0) {
    unsigned i = blockIdx.x * blockDim.x + threadIdx.x;   // 131072
    unsigned b = i & 127, row = (i >> 7) & 127, n = i >> 14;
    unsigned kc = row >> 4, kb = (row >> 2) & 3, kk = row & 3;
    unsigned k0 = kc * 64 + kb * 16 + 2 * kk;
    const float* src = hn0 + ((size_t)(n * 128 + b)) * 512;
    uint2 v;
    v.x = packf16(src[k0],     src[k0 + 1]);
    v.y = packf16(src[k0 + 8], src[k0 + 9]);
    g_ht[0][n][row][b ^ (kk << 2)] = v;
    if (i < NBR * 32) g_bar[i] = 0;
}

// ---------------- prep: transpose x ----------------
__global__ void prep_x_kernel(const float* __restrict__ cin) {
    unsigned i = blockIdx.x * blockDim.x + threadIdx.x;   // 32768
    unsigned b = i & 127, t = i >> 7;
    g_xt[t * BATCH + b] = cin[b * TT + t];
}

// ---------------- cp.async issue helpers (1024 x 16B each, 512 threads) ----------------
__device__ __forceinline__ void issue_W(uint32_t dst, const uint4* srcW, int kc, int tid) {
    #pragma unroll
    for (int r = 0; r < 2; r++) {
        int i = r * THREADS + tid;
        cp16(dst + i * 16, srcW + kc * 1024 + i);
    }
}
__device__ __forceinline__ void issue_B(uint32_t dst, const uint4* srcB, int kc, int tid) {
    #pragma unroll
    for (int r = 0; r < 2; r++) {
        int i = r * THREADS + tid;
        cp16(dst + OFF_B + i * 16, srcB + kc * 1024 + i);
    }
}

// ---------------- persistent kernel: all 256 LSTM steps ----------------
// grid 128 = n*16 + jt. 16 warps: wm = wid&3 (mt = wm*2..+1), wb = wid>>2 (32-col slice).
__global__ __launch_bounds__(THREADS, 1)
void steps_kernel(const float* __restrict__ Wih, const float* __restrict__ b_ih,
                  const float* __restrict__ b_hh)
{
    extern __shared__ __align__(16) unsigned char smem_raw[];
    uint32_t sb = smem_u32(smem_raw);
    uint32_t base = (sb + 1023) & ~1023u;
    unsigned char* bp = smem_raw + (base - sb);

    const int tid = threadIdx.x, wid = tid >> 5, lane = tid & 31;
    const int n = blockIdx.x >> 4, jt = blockIdx.x & 15;
    const int wm = wid & 3, wb = wid >> 2;
    const int q = lane >> 2, lr = lane & 3;      // q = gid, lr = tig/kk

    float*  smx  = (float*)(bp + OFF_X);
    float2* smwb = (float2*)(bp + OFF_WB);
    float*  smh  = (float*)(bp + OFF_H);

    if (tid < 128) {
        int gg = tid >> 5, jj = tid & 31;
        int row = n * G4 + gg * HID + jt * 32 + jj;
        smwb[tid] = make_float2(Wih[row], b_ih[row] + b_hh[row]);
    }
    __syncthreads();

    // per-thread gate constants (gates gA = q>>2 in {0,1} and gA+2)
    float2 wbA[2], wbB[2];
    {
        const int gA = q >> 2;
        #pragma unroll
        for (int m2 = 0; m2 < 2; m2++) {
            int jj = (wm * 2 + m2) * 4 + (q & 3);
            wbA[m2] = smwb[gA * 32 + jj];
            wbB[m2] = smwb[(gA + 2) * 32 + jj];
        }
    }

    // register-resident cell state (valid on lanes >= 16)
    float creg[2][4][2];
    #pragma unroll
    for (int a = 0; a < 2; a++)
        #pragma unroll
        for (int b2 = 0; b2 < 4; b2++) { creg[a][b2][0] = 0.0f; creg[a][b2][1] = 0.0f; }

    const uint4* srcW = &g_wimg[n][jt][0][0];

    // prologue: chunks 0,1 -> stages 0,1
    {
        const uint4* sB = (const uint4*)&g_ht[0][n][0][0];
        issue_W(base, srcW, 0, tid);
        issue_B(base, sB, 0, tid);
        CP_COMMIT();
        issue_W(base + STAGE, srcW, 1, tid);
        issue_B(base + STAGE, sB, 1, tid);
        CP_COMMIT();
    }

    int stg = 0;

    #pragma unroll 1
    for (int t = 0; t < TT; t++) {
        const int s = t & 1, dd = s ^ 1;
        const uint4* srcB = (const uint4*)&g_ht[s][n][0][0];

        if (tid < 128) smx[tid] = g_xt[t * BATCH + tid];

        float acc[2][4][4];
        #pragma unroll
        for (int a0 = 0; a0 < 2; a0++)
            #pragma unroll
            for (int a1 = 0; a1 < 4; a1++)
                #pragma unroll
                for (int a2 = 0; a2 < 4; a2++) acc[a0][a1][a2] = 0.0f;

        #pragma unroll 1
        for (int kc = 0; kc < 8; kc++) {
            CP_WAIT(1);
            __syncthreads();

            int istg = stg + 2; if (istg >= 3) istg -= 3;
            uint32_t dst = base + (uint32_t)istg * STAGE;
            if (kc < 6) {
                issue_W(dst, srcW, kc + 2, tid);
                issue_B(dst, srcB, kc + 2, tid);
                CP_COMMIT();
            } else if (t < TT - 1 || kc == 6) {
                issue_W(dst, srcW, kc - 6, tid);    // next step's W chunk 0/1
                CP_COMMIT();
            }

            const uint32_t tb = base + (uint32_t)stg * STAGE;
            #pragma unroll
            for (int kb = 0; kb < 4; kb++) {
                uint32_t Af[2][4];
                #pragma unroll
                for (int m2 = 0; m2 < 2; m2++) {
                    uint32_t ad = tb + (uint32_t)(((kb * 8 + (wm * 2 + m2)) * 32 + lane) * 16);
                    asm volatile("ld.shared.v4.b32 {%0,%1,%2,%3}, [%4];"
                        : "=r"(Af[m2][0]), "=r"(Af[m2][1]), "=r"(Af[m2][2]), "=r"(Af[m2][3])
                        : "r"(ad));
                }
                uint32_t Bf[4][2];
                #pragma unroll
                for (int nt = 0; nt < 4; nt++) {
                    int colp = (wb * 32 + nt * 8 + q) ^ (lr << 2);
                    uint32_t ad = tb + OFF_B + (uint32_t)(((kb * 4 + lr) * 128 + colp) * 8);
                    asm volatile("ld.shared.v2.b32 {%0,%1}, [%2];"
                        : "=r"(Bf[nt][0]), "=r"(Bf[nt][1]) : "r"(ad));
                }
                #pragma unroll
                for (int m2 = 0; m2 < 2; m2++)
                    #pragma unroll
                    for (int nt = 0; nt < 4; nt++)
                        mma_f16(acc[m2][nt], Af[m2], Bf[nt]);
            }
            stg = (stg + 1 == 3) ? 0 : stg + 1;
        }

        // ---- epilogue: gates in regs, shfl pair (i,g)<->(f,o), cell in regs ----
        #pragma unroll
        for (int m2 = 0; m2 < 2; m2++) {
            #pragma unroll
            for (int nt = 0; nt < 4; nt++) {
                int col = wb * 32 + nt * 8 + lr * 2;
                float hv[2];
                #pragma unroll
                for (int cp = 0; cp < 2; cp++) {
                    float xv = smx[col + cp];
                    float v0 = acc[m2][nt][cp]     + xv * wbA[m2].x + wbA[m2].y;
                    float v1 = acc[m2][nt][2 + cp] + xv * wbB[m2].x + wbB[m2].y;
                    float sv0 = sigm(v0);                      // sigm(i) | sigm(f)
                    float a1 = (lane < 16) ? (-2.0f * v1) : (-v1);
                    float e1 = __expf(a1);
                    float w1 = (lane < 16) ? (2.0f / (1.0f + e1) - 1.0f)   // tanh(g)
                                           : (1.0f / (1.0f + e1));          // sigm(o)
                    float pv = sv0 * w1;                        // lanes<16: sigm(i)*tanh(g)
                    float rcv = __shfl_xor_sync(0xffffffffu, pv, 16);
                    float cn = sv0 * creg[m2][nt][cp] + rcv;    // lanes>=16 valid
                    creg[m2][nt][cp] = cn;
                    hv[cp] = w1 * tanh_(cn);                    // lanes>=16: sigm(o)*tanh(cn)
                }
                if (lane >= 16) {
                    int jj = (wm * 2 + m2) * 4 + (q & 3);
                    *(float2*)&smh[jj * 132 + col] = make_float2(hv[0], hv[1]);
                }
            }
        }
        __syncthreads();

        // ---- h writeout: fp16-pack into g_ht[dd] (B-fragment gmem layout) ----
        #pragma unroll
        for (int w2 = 0; w2 < 2; w2++) {
            int id = w2 * THREADS + tid;        // 0..1023
            int rowl = id >> 7;                 // 0..7
            int b  = id & 127;
            int kbl = rowl >> 2, kk = rowl & 3;
            int jb = kbl * 16 + 2 * kk;         // local j base
            float h0 = smh[jb * 132 + b];
            float h1 = smh[(jb + 1) * 132 + b];
            float h2 = smh[(jb + 8) * 132 + b];
            float h3 = smh[(jb + 9) * 132 + b];
            uint2 v;
            v.x = packf16(h0, h1);
            v.y = packf16(h2, h3);
            int rowg = (jt >> 1) * 16 + (2 * (jt & 1) + kbl) * 4 + kk;
            g_ht[dd][n][rowg][b ^ (kk << 2)] = v;
        }
        if (jt == 15 && tid < 128)
            g_ys[(size_t)t * NBR * BATCH + n * BATCH + tid] = smh[31 * 132 + tid];  // h[j=511]
        __syncthreads();

        // ---- per-branch barrier (16 CTAs), then next step's B chunks 0,1 ----
        if (t < TT - 1) {
            if (tid == 0) {
                __threadfence();
                atomicAdd(&g_bar[n * 32], 1u);
                const unsigned tgt = 16u * (unsigned)(t + 1);
                unsigned v;
                do {
                    asm volatile("ld.acquire.gpu.global.u32 %0, [%1];"
                        : "=r"(v) : "l"(g_bar + n * 32) : "memory");
                } while (v < tgt);
            }
            __syncthreads();
            const uint4* nB = (const uint4*)&g_ht[dd][n][0][0];
            issue_B(base + (uint32_t)stg * STAGE, nB, 0, tid);
            CP_COMMIT();
            int st1 = (stg + 1 == 3) ? 0 : stg + 1;
            issue_B(base + (uint32_t)st1 * STAGE, nB, 1, tid);
            CP_COMMIT();
        }
    }
    CP_WAIT(0);
    __syncthreads();
}

// ---------------- readout ----------------
__global__ void final_kernel(const float* __restrict__ x, const float* __restrict__ Wl,
                             const float* __restrict__ bl, float* __restrict__ out)
{
    __shared__ float red[TT];
    const int b = blockIdx.x;
    const int t = threadIdx.x;
    float r = 0.0f;
    #pragma unroll
    for (int nn = 0; nn < NBR; nn++)
        r += g_ys[(size_t)t * NBR * BATCH + nn * BATCH + b] * x[(nn * BATCH + b) * TT + t];
    for (int k = 0; k < NBR; k++) {
        red[t] = r * Wl[k * TT + t];
        __syncthreads();
        for (int sft = TT / 2; sft > 0; sft >>= 1) {
            if (t < sft) red[t] += red[t + sft];
            __syncthreads();
        }
        if (t == 0) out[b * NBR + k] = red[0] + bl[k];
        __syncthreads();
    }
}

// ---------------- launch ----------------
extern "C" void kernel_launch(void* const* d_in, const int* in_sizes, int n_in,
                              void* d_out, int out_size)
{
    (void)in_sizes; (void)n_in; (void)out_size;
    const float* x    = (const float*)d_in[0];
    const float* c    = (const float*)d_in[1];
    const float* Wih  = (const float*)d_in[2];
    const float* Whh  = (const float*)d_in[3];
    const float* b_ih = (const float*)d_in[4];
    const float* b_hh = (const float*)d_in[5];
    const float* hn0  = (const float*)d_in[6];
    const float* Wl   = (const float*)d_in[7];
    const float* bl   = (const float*)d_in[8];
    float* out = (float*)d_out;

    static bool attr_set = false;
    if (!attr_set) {
        cudaFuncSetAttribute(steps_kernel, cudaFuncAttributeMaxDynamicSharedMemorySize, DSMEM_REQ);
        attr_set = true;
    }

    prep_w_kernel<<<4096, 256>>>(Whh);
    prep_h_kernel<<<512, 256>>>(hn0);
    prep_x_kernel<<<128, 256>>>(c);
    steps_kernel<<<128, THREADS, DSMEM_REQ>>>(Wih, b_ih, b_hh);
    final_kernel<<<BATCH, TT>>>(x, Wl, bl, out);
}

// round 15
// speedup vs baseline: 4.6557x; 1.0121x over previous
#include <cuda_runtime.h>
#include <cstdint>

#define NBR    8
#define BATCH  128
#define HID    512
#define TT     256
#define G4     2048
#define THREADS 512

// ---------------- device scratch (static, no runtime alloc) ----------------
// h state fp16, B-fragment layout: g_ht[s][n][row][colp] (uint2),
// row = kc*16 + kb*4 + kk; uint2 = {f16x2(k=2kk,2kk+1 | b), f16x2(k=2kk+8,2kk+9 | b)},
// k relative to kb16 block; colp = b ^ (kk<<2). Ping-pong on step parity.
__device__ __align__(16) uint2 g_ht[2][NBR][128][128];
__device__ __align__(16) float g_ys[TT*NBR*BATCH];
__device__ __align__(16) float g_xt[TT*BATCH];          // x transposed: [t][b]
__device__ unsigned g_bar[NBR*32];
// Whh fp16, A-fragment layout (gate-interleaved row permutation):
// per (n,jt): [kc 8][kb 4][mt 8][lane 32] uint4 = {a0,a1,a2,a3}
__device__ __align__(16) uint4 g_wimg[NBR][16][8192];

// ---------------- helpers ----------------
__device__ __forceinline__ float sigm(float x)  { return 1.0f / (1.0f + __expf(-x)); }
__device__ __forceinline__ float tanh_(float x) { return 2.0f / (1.0f + __expf(-2.0f * x)) - 1.0f; }

__device__ __forceinline__ uint32_t smem_u32(const void* p) {
    uint32_t a;
    asm("{ .reg .u64 t; cvta.to.shared.u64 t, %1; cvt.u32.u64 %0, t; }" : "=r"(a) : "l"(p));
    return a;
}
// pack two fp32 -> f16x2 {lo, hi}
__device__ __forceinline__ uint32_t packf16(float lo, float hi) {
    uint32_t r; asm("cvt.rn.f16x2.f32 %0, %1, %2;" : "=r"(r) : "f"(hi), "f"(lo)); return r;
}
__device__ __forceinline__ void cp16(uint32_t dst, const void* src) {
    asm volatile("cp.async.cg.shared.global [%0], [%1], 16;" :: "r"(dst), "l"(src) : "memory");
}
#define CP_COMMIT() asm volatile("cp.async.commit_group;" ::: "memory")
#define CP_WAIT(N)  asm volatile("cp.async.wait_group %0;" :: "n"(N) : "memory")

__device__ __forceinline__ void mma_f16(float* d, const uint32_t* a, const uint32_t* b) {
    asm volatile("mma.sync.aligned.m16n8k16.row.col.f32.f16.f16.f32 "
        "{%0,%1,%2,%3}, {%4,%5,%6,%7}, {%8,%9}, {%0,%1,%2,%3};"
        : "+f"(d[0]), "+f"(d[1]), "+f"(d[2]), "+f"(d[3])
        : "r"(a[0]), "r"(a[1]), "r"(a[2]), "r"(a[3]), "r"(b[0]), "r"(b[1]));
}

// ---------------- SMEM layout ----------------
// [0, 131072): W resident (8 chunks x 16 KB, A-fragment layout)
// [131072, 196608): B ring, 4 stages x 16 KB
#define OFF_BST 131072
#define BSTAGE  16384
#define OFF_X   196608        // 512 B
#define OFF_WB  197120        // float2[128] = 1 KB
#define OFF_H   198144        // float[32][132] = 16896 B
#define DSMEM_REQ 216064

// ---------------- prep: Whh -> fp16 A-fragments, permuted ----------------
__global__ void prep_w_kernel(const float* __restrict__ Whh) {
    unsigned i = blockIdx.x * blockDim.x + threadIdx.x;   // 2^20
    unsigned lane = i & 31, mt = (i >> 5) & 7, kb = (i >> 8) & 3;
    unsigned kc = (i >> 10) & 7, jt = (i >> 13) & 15, n = i >> 17;
    unsigned gid = lane >> 2, tig = lane & 3;
    unsigned g0 = gid >> 2, jl = gid & 3;
    unsigned j = jt * 32 + mt * 4 + jl;
    const float* rA = Whh + ((size_t)(n * G4 + g0 * HID + j)) * HID;        // gate g0
    const float* rB = Whh + ((size_t)(n * G4 + (g0 + 2) * HID + j)) * HID;  // gate g0+2
    unsigned k0 = kc * 64 + kb * 16 + 2 * tig;
    uint4 v;
    v.x = packf16(rA[k0],     rA[k0 + 1]);
    v.y = packf16(rB[k0],     rB[k0 + 1]);
    v.z = packf16(rA[k0 + 8], rA[k0 + 9]);
    v.w = packf16(rB[k0 + 8], rB[k0 + 9]);
    g_wimg[n][jt][kc * 1024 + (kb * 8 + mt) * 32 + lane] = v;
}

// ---------------- prep: h0 -> fp16 packed, barrier reset ----------------
__global__ void prep_h_kernel(const float* __restrict__ hn0) {
    unsigned i = blockIdx.x * blockDim.x + threadIdx.x;   // 131072
    unsigned b = i & 127, row = (i >> 7) & 127, n = i >> 14;
    unsigned kc = row >> 4, kb = (row >> 2) & 3, kk = row & 3;
    unsigned k0 = kc * 64 + kb * 16 + 2 * kk;
    const float* src = hn0 + ((size_t)(n * 128 + b)) * 512;
    uint2 v;
    v.x = packf16(src[k0],     src[k0 + 1]);
    v.y = packf16(src[k0 + 8], src[k0 + 9]);
    g_ht[0][n][row][b ^ (kk << 2)] = v;
    if (i < NBR * 32) g_bar[i] = 0;
}

// ---------------- prep: transpose x ----------------
__global__ void prep_x_kernel(const float* __restrict__ cin) {
    unsigned i = blockIdx.x * blockDim.x + threadIdx.x;   // 32768
    unsigned b = i & 127, t = i >> 7;
    g_xt[t * BATCH + b] = cin[b * TT + t];
}

// ---------------- cp.async issue helper: one B chunk (1024 x 16B) ----------------
__device__ __forceinline__ void issue_B(uint32_t base, const uint2* srcB, int kc, int tid) {
    uint32_t dst = base + OFF_BST + (uint32_t)(kc & 3) * BSTAGE;
    const uint4* s = (const uint4*)(srcB + (size_t)kc * 2048);
    #pragma unroll
    for (int r = 0; r < 2; r++) {
        int i = r * THREADS + tid;
        cp16(dst + i * 16, s + i);
    }
    CP_COMMIT();
}

// ---------------- persistent kernel: all 256 LSTM steps ----------------
// grid 128 = n*16 + jt. 16 warps: wm = wid&3 (mt = wm*2..+1), wb = wid>>2 (32-col slice).
__global__ __launch_bounds__(THREADS, 1)
void steps_kernel(const float* __restrict__ Wih, const float* __restrict__ b_ih,
                  const float* __restrict__ b_hh)
{
    extern __shared__ __align__(16) unsigned char smem_raw[];
    uint32_t sb = smem_u32(smem_raw);
    uint32_t base = (sb + 1023) & ~1023u;
    unsigned char* bp = smem_raw + (base - sb);

    const int tid = threadIdx.x, wid = tid >> 5, lane = tid & 31;
    const int n = blockIdx.x >> 4, jt = blockIdx.x & 15;
    const int wm = wid & 3, wb = wid >> 2;
    const int q = lane >> 2, lr = lane & 3;      // q = gid, lr = tig/kk

    float*  smx  = (float*)(bp + OFF_X);
    float2* smwb = (float2*)(bp + OFF_WB);
    float*  smh  = (float*)(bp + OFF_H);

    if (tid < 128) {
        int gg = tid >> 5, jj = tid & 31;
        int row = n * G4 + gg * HID + jt * 32 + jj;
        smwb[tid] = make_float2(Wih[row], b_ih[row] + b_hh[row]);
    }
    __syncthreads();

    // per-thread gate constants (gates gA = q>>2 in {0,1} and gA+2)
    float2 wbA[2], wbB[2];
    {
        const int gA = q >> 2;
        #pragma unroll
        for (int m2 = 0; m2 < 2; m2++) {
            int jj = (wm * 2 + m2) * 4 + (q & 3);
            wbA[m2] = smwb[gA * 32 + jj];
            wbB[m2] = smwb[(gA + 2) * 32 + jj];
        }
    }

    // register-resident cell state (valid on lanes >= 16)
    float creg[2][4][2];
    #pragma unroll
    for (int a = 0; a < 2; a++)
        #pragma unroll
        for (int b2 = 0; b2 < 4; b2++) { creg[a][b2][0] = 0.0f; creg[a][b2][1] = 0.0f; }

    // ---- load W once: 8192 uint4 = 128 KB resident for all 256 steps ----
    {
        const uint4* srcW = &g_wimg[n][jt][0];
        #pragma unroll
        for (int r = 0; r < 16; r++) {
            int i = r * THREADS + tid;
            cp16(base + i * 16, srcW + i);
        }
        CP_COMMIT();
    }
    // prologue: B chunks 0..2 of step 0
    {
        const uint2* sB = &g_ht[0][n][0][0];
        issue_B(base, sB, 0, tid);
        issue_B(base, sB, 1, tid);
        issue_B(base, sB, 2, tid);
    }

    #pragma unroll 1
    for (int t = 0; t < TT; t++) {
        const int s = t & 1, dd = s ^ 1;
        const uint2* srcB = &g_ht[s][n][0][0];

        if (tid < 128) smx[tid] = g_xt[t * BATCH + tid];

        float acc[2][4][4];
        #pragma unroll
        for (int a0 = 0; a0 < 2; a0++)
            #pragma unroll
            for (int a1 = 0; a1 < 4; a1++)
                #pragma unroll
                for (int a2 = 0; a2 < 4; a2++) acc[a0][a1][a2] = 0.0f;

        #pragma unroll 1
        for (int kc = 0; kc < 8; kc++) {
            if (kc < 6)      CP_WAIT(2);
            else if (kc == 6) CP_WAIT(1);
            else              CP_WAIT(0);
            __syncthreads();

            if (kc < 5) issue_B(base, srcB, kc + 3, tid);

            const uint32_t wbase = base + (uint32_t)kc * BSTAGE;            // W chunk kc
            const uint32_t bst   = base + OFF_BST + (uint32_t)(kc & 3) * BSTAGE;
            #pragma unroll
            for (int kb = 0; kb < 4; kb++) {
                uint32_t Af[2][4];
                #pragma unroll
                for (int m2 = 0; m2 < 2; m2++) {
                    uint32_t ad = wbase + (uint32_t)(((kb * 8 + (wm * 2 + m2)) * 32 + lane) * 16);
                    asm volatile("ld.shared.v4.b32 {%0,%1,%2,%3}, [%4];"
                        : "=r"(Af[m2][0]), "=r"(Af[m2][1]), "=r"(Af[m2][2]), "=r"(Af[m2][3])
                        : "r"(ad));
                }
                uint32_t Bf[4][2];
                #pragma unroll
                for (int nt = 0; nt < 4; nt++) {
                    int colp = (wb * 32 + nt * 8 + q) ^ (lr << 2);
                    uint32_t ad = bst + (uint32_t)(((kb * 4 + lr) * 128 + colp) * 8);
                    asm volatile("ld.shared.v2.b32 {%0,%1}, [%2];"
                        : "=r"(Bf[nt][0]), "=r"(Bf[nt][1]) : "r"(ad));
                }
                #pragma unroll
                for (int m2 = 0; m2 < 2; m2++)
                    #pragma unroll
                    for (int nt = 0; nt < 4; nt++)
                        mma_f16(acc[m2][nt], Af[m2], Bf[nt]);
            }
        }

        // ---- epilogue: gates in regs, shfl pair (i,g)<->(f,o), cell in regs ----
        #pragma unroll
        for (int m2 = 0; m2 < 2; m2++) {
            #pragma unroll
            for (int nt = 0; nt < 4; nt++) {
                int col = wb * 32 + nt * 8 + lr * 2;
                float hv[2];
                #pragma unroll
                for (int cp = 0; cp < 2; cp++) {
                    float xv = smx[col + cp];
                    float v0 = acc[m2][nt][cp]     + xv * wbA[m2].x + wbA[m2].y;
                    float v1 = acc[m2][nt][2 + cp] + xv * wbB[m2].x + wbB[m2].y;
                    float sv0 = sigm(v0);                      // sigm(i) | sigm(f)
                    float a1 = (lane < 16) ? (-2.0f * v1) : (-v1);
                    float e1 = __expf(a1);
                    float w1 = (lane < 16) ? (2.0f / (1.0f + e1) - 1.0f)   // tanh(g)
                                           : (1.0f / (1.0f + e1));          // sigm(o)
                    float pv = sv0 * w1;                        // lanes<16: sigm(i)*tanh(g)
                    float rcv = __shfl_xor_sync(0xffffffffu, pv, 16);
                    float cn = sv0 * creg[m2][nt][cp] + rcv;    // lanes>=16 valid
                    creg[m2][nt][cp] = cn;
                    hv[cp] = w1 * tanh_(cn);                    // lanes>=16: sigm(o)*tanh(cn)
                }
                if (lane >= 16) {
                    int jj = (wm * 2 + m2) * 4 + (q & 3);
                    *(float2*)&smh[jj * 132 + col] = make_float2(hv[0], hv[1]);
                }
            }
        }
        __syncthreads();

        // ---- h writeout: fp16-pack into g_ht[dd] (B-fragment gmem layout) ----
        #pragma unroll
        for (int w2 = 0; w2 < 2; w2++) {
            int id = w2 * THREADS + tid;        // 0..1023
            int rowl = id >> 7;                 // 0..7
            int b  = id & 127;
            int kbl = rowl >> 2, kk = rowl & 3;
            int jb = kbl * 16 + 2 * kk;         // local j base
            float h0 = smh[jb * 132 + b];
            float h1 = smh[(jb + 1) * 132 + b];
            float h2 = smh[(jb + 8) * 132 + b];
            float h3 = smh[(jb + 9) * 132 + b];
            uint2 v;
            v.x = packf16(h0, h1);
            v.y = packf16(h2, h3);
            int rowg = (jt >> 1) * 16 + (2 * (jt & 1) + kbl) * 4 + kk;
            g_ht[dd][n][rowg][b ^ (kk << 2)] = v;
        }
        if (jt == 15 && tid < 128)
            g_ys[(size_t)t * NBR * BATCH + n * BATCH + tid] = smh[31 * 132 + tid];  // h[j=511]
        __syncthreads();

        // ---- per-branch barrier (16 CTAs), then next step's B chunks 0..2 ----
        if (t < TT - 1) {
            if (tid == 0) {
                __threadfence();
                atomicAdd(&g_bar[n * 32], 1u);
                const unsigned tgt = 16u * (unsigned)(t + 1);
                unsigned v;
                do {
                    asm volatile("ld.acquire.gpu.global.u32 %0, [%1];"
                        : "=r"(v) : "l"(g_bar + n * 32) : "memory");
                } while (v < tgt);
            }
            __syncthreads();
            const uint2* nB = &g_ht[dd][n][0][0];
            issue_B(base, nB, 0, tid);
            issue_B(base, nB, 1, tid);
            issue_B(base, nB, 2, tid);
        }
    }
    CP_WAIT(0);
    __syncthreads();
}

// ---------------- readout ----------------
__global__ void final_kernel(const float* __restrict__ x, const float* __restrict__ Wl,
                             const float* __restrict__ bl, float* __restrict__ out)
{
    __shared__ float red[TT];
    const int b = blockIdx.x;
    const int t = threadIdx.x;
    float r = 0.0f;
    #pragma unroll
    for (int nn = 0; nn < NBR; nn++)
        r += g_ys[(size_t)t * NBR * BATCH + nn * BATCH + b] * x[(nn * BATCH + b) * TT + t];
    for (int k = 0; k < NBR; k++) {
        red[t] = r * Wl[k * TT + t];
        __syncthreads();
        for (int sft = TT / 2; sft > 0; sft >>= 1) {
            if (t < sft) red[t] += red[t + sft];
            __syncthreads();
        }
        if (t == 0) out[b * NBR + k] = red[0] + bl[k];
        __syncthreads();
    }
}

// ---------------- launch ----------------
extern "C" void kernel_launch(void* const* d_in, const int* in_sizes, int n_in,
                              void* d_out, int out_size)
{
    (void)in_sizes; (void)n_in; (void)out_size;
    const float* x    = (const float*)d_in[0];
    const float* c    = (const float*)d_in[1];
    const float* Wih  = (const float*)d_in[2];
    const float* Whh  = (const float*)d_in[3];
    const float* b_ih = (const float*)d_in[4];
    const float* b_hh = (const float*)d_in[5];
    const float* hn0  = (const float*)d_in[6];
    const float* Wl   = (const float*)d_in[7];
    const float* bl   = (const float*)d_in[8];
    float* out = (float*)d_out;

    static bool attr_set = false;
    if (!attr_set) {
        cudaFuncSetAttribute(steps_kernel, cudaFuncAttributeMaxDynamicSharedMemorySize, DSMEM_REQ);
        attr_set = true;
    }

    prep_w_kernel<<<4096, 256>>>(Whh);
    prep_h_kernel<<<512, 256>>>(hn0);
    prep_x_kernel<<<128, 256>>>(c);
    steps_kernel<<<128, THREADS, DSMEM_REQ>>>(Wih, b_ih, b_hh);
    final_kernel<<<BATCH, TT>>>(x, Wl, bl, out);
}